// round 2
// baseline (speedup 1.0000x reference)
#include <cuda_runtime.h>

// ---------------- scratch (device globals; no allocation allowed) ----------------
__device__ __align__(16) float g_h1[128*32*20*20];          // conv1+  (1 timestep)
__device__ __align__(16) float g_s1[8*128*32*20*20];        // spikes layer1 [t][b][c][p]
__device__ __align__(16) float g_h2[8*128*64*9*9];          // conv2 out [tb][c][p]
__device__ __align__(16) float g_s2[8*128*64*9*9];
__device__ __align__(16) float g_h3[8*128*64*7*7];
__device__ __align__(16) float g_s3[8*128*64*7*7];
__device__ __align__(16) float g_h4[8*128*512];
__device__ __align__(16) float g_cnt[128*512];
__device__ float g_mean1[32], g_rstd1[32];
__device__ float g_mean2[64], g_rstd2[64];
__device__ float g_mean3[64], g_rstd3[64];

// ---------------- conv1: [128,4,84,84] -> [128,32,20,20], k8 s4 ----------------
// one block per image; input + transposed weights in smem; 8oc x 4pos per thread
#define SMEM1 ((28224 + 256*33)*4)
__global__ void __launch_bounds__(256) k_conv1(const float* __restrict__ x,
                                               const float* __restrict__ w,
                                               const float* __restrict__ bias)
{
    extern __shared__ float sm[];
    float* s_in = sm;             // 4*84*84 = 28224
    float* s_w  = sm + 28224;     // [tap(256)][oc(32)] pitch 33
    const int n = blockIdx.x, tid = threadIdx.x;

    const float4* gx = (const float4*)(x + n*28224);
    for (int i = tid; i < 7056; i += 256) ((float4*)s_in)[i] = gx[i];
    for (int i = tid; i < 8192; i += 256) {
        int oc = i >> 8, tap = i & 255;
        s_w[tap*33 + oc] = w[i];
    }
    __syncthreads();

    for (int task = tid; task < 400; task += 256) {
        int ocg = task & 3, posg = task >> 2;
        int oc0 = ocg * 8, p0 = posg * 4;
        float acc[8][4];
        #pragma unroll
        for (int i = 0; i < 8; i++)
            #pragma unroll
            for (int j = 0; j < 4; j++) acc[i][j] = 0.f;
        int base[4];
        #pragma unroll
        for (int j = 0; j < 4; j++) {
            int p = p0 + j, oy = p / 20, ox = p - oy*20;
            base[j] = oy*4*84 + ox*4;
        }
        for (int ic = 0; ic < 4; ic++) {
            #pragma unroll
            for (int ky = 0; ky < 8; ky++) {
                int ib = ic*7056 + ky*84;
                const float* wrow = s_w + (ic*64 + ky*8)*33 + oc0;
                #pragma unroll
                for (int kx = 0; kx < 8; kx++) {
                    float in0 = s_in[base[0]+ib+kx];
                    float in1 = s_in[base[1]+ib+kx];
                    float in2 = s_in[base[2]+ib+kx];
                    float in3 = s_in[base[3]+ib+kx];
                    const float* wp = wrow + kx*33;
                    #pragma unroll
                    for (int i = 0; i < 8; i++) {
                        float wf = wp[i];
                        acc[i][0] += wf*in0; acc[i][1] += wf*in1;
                        acc[i][2] += wf*in2; acc[i][3] += wf*in3;
                    }
                }
            }
        }
        #pragma unroll
        for (int i = 0; i < 8; i++) {
            float bb = bias[oc0+i];
            #pragma unroll
            for (int j = 0; j < 4; j++)
                g_h1[(n*32 + oc0+i)*400 + p0 + j] = acc[i][j] + bb;
        }
    }
}

// ---------------- BN statistics: one block per channel ----------------
__global__ void __launch_bounds__(256) k_bnstats(int sel, int N, int C, int S)
{
    const float* h = (sel == 0) ? g_h1 : (sel == 1) ? g_h2 : g_h3;
    float* mean = (sel == 0) ? g_mean1 : (sel == 1) ? g_mean2 : g_mean3;
    float* rstd = (sel == 0) ? g_rstd1 : (sel == 1) ? g_rstd2 : g_rstd3;
    int c = blockIdx.x, tid = threadIdx.x;
    int total = N * S;
    float sum = 0.f, sq = 0.f;
    for (int i = tid; i < total; i += 256) {
        int n = i / S, s = i - n*S;
        float v = h[(n*C + c)*S + s];
        sum += v; sq += v*v;
    }
    __shared__ float ss[512];
    ss[tid] = sum; ss[256+tid] = sq;
    __syncthreads();
    for (int k = 128; k > 0; k >>= 1) {
        if (tid < k) { ss[tid] += ss[tid+k]; ss[256+tid] += ss[256+tid+k]; }
        __syncthreads();
    }
    if (tid == 0) {
        float m = ss[0] / (float)total;
        float var = ss[256] / (float)total - m*m;
        mean[c] = m;
        rstd[c] = rsqrtf(var + 1e-5f);
    }
}

// ---------------- LIF layer 1 (input constant over t) ----------------
__global__ void k_lif1(const float* __restrict__ gamma, const float* __restrict__ beta)
{
    int idx = blockIdx.x*blockDim.x + threadIdx.x;
    if (idx >= 128*32*400) return;
    int c = (idx / 400) & 31;
    float a = (g_h1[idx] - g_mean1[c]) * g_rstd1[c] * gamma[c] + beta[c];
    float v = 0.f;
    #pragma unroll
    for (int t = 0; t < 8; t++) {
        v = v + (a - v)*0.5f;
        float s = (v >= 1.0f) ? 1.0f : 0.0f;
        g_s1[t*1638400 + idx] = s;
        v = v * (1.0f - s);
    }
}

// ---------------- conv2: [1024,32,20,20] -> [1024,64,9,9], k4 s2 ----------------
#define SMEM2 ((12800 + 512*65)*4)
__global__ void __launch_bounds__(256) k_conv2(const float* __restrict__ w,
                                               const float* __restrict__ bias)
{
    extern __shared__ float sm[];
    float* s_in = sm;             // 32*20*20 = 12800
    float* s_w  = sm + 12800;     // [tap(512)][oc(64)] pitch 65
    const int tb = blockIdx.x, tid = threadIdx.x;

    const float4* gin = (const float4*)(g_s1 + tb*12800);
    for (int i = tid; i < 3200; i += 256) ((float4*)s_in)[i] = gin[i];
    for (int i = tid; i < 32768; i += 256) {
        int oc = i >> 9, tap = i & 511;
        s_w[tap*65 + oc] = w[i];
    }
    __syncthreads();

    int task = tid;   // 216 tasks: 8 oc-groups x 27 pos-groups(3)
    if (task < 216) {
        int ocg = task & 7, posg = task >> 3;
        int oc0 = ocg * 8, p0 = posg * 3;
        float acc[8][3];
        #pragma unroll
        for (int i = 0; i < 8; i++)
            #pragma unroll
            for (int j = 0; j < 3; j++) acc[i][j] = 0.f;
        int base[3];
        #pragma unroll
        for (int j = 0; j < 3; j++) {
            int p = p0 + j, oy = p / 9, ox = p - oy*9;
            base[j] = oy*2*20 + ox*2;
        }
        for (int ic = 0; ic < 32; ic++) {
            #pragma unroll
            for (int ky = 0; ky < 4; ky++) {
                int ib = ic*400 + ky*20;
                const float* wrow = s_w + (ic*16 + ky*4)*65 + oc0;
                #pragma unroll
                for (int kx = 0; kx < 4; kx++) {
                    float in0 = s_in[base[0]+ib+kx];
                    float in1 = s_in[base[1]+ib+kx];
                    float in2 = s_in[base[2]+ib+kx];
                    const float* wp = wrow + kx*65;
                    #pragma unroll
                    for (int i = 0; i < 8; i++) {
                        float wf = wp[i];
                        acc[i][0] += wf*in0; acc[i][1] += wf*in1; acc[i][2] += wf*in2;
                    }
                }
            }
        }
        #pragma unroll
        for (int i = 0; i < 8; i++) {
            float bb = bias[oc0+i];
            #pragma unroll
            for (int j = 0; j < 3; j++)
                g_h2[(tb*64 + oc0+i)*81 + p0 + j] = acc[i][j] + bb;
        }
    }
}

// ---------------- LIF layer 2 ----------------
__global__ void k_lif2(const float* __restrict__ gamma, const float* __restrict__ beta)
{
    int idx = blockIdx.x*blockDim.x + threadIdx.x;
    if (idx >= 128*5184) return;
    int b = idx / 5184;
    int r = idx - b*5184;
    int c = r / 81;
    float m = g_mean2[c], rs = g_rstd2[c], ga = gamma[c], be = beta[c];
    float v = 0.f;
    #pragma unroll
    for (int t = 0; t < 8; t++) {
        int j = (t*128 + b)*5184 + r;
        float a = (g_h2[j] - m) * rs * ga + be;
        v = v + (a - v)*0.5f;
        float s = (v >= 1.0f) ? 1.0f : 0.0f;
        g_s2[j] = s;
        v = v * (1.0f - s);
    }
}

// ---------------- conv3: [1024,64,9,9] -> [1024,64,7,7], k3 s1 ----------------
// grid (1024, 2): blockIdx.y selects a half of the 64 output channels
#define SMEM3 ((5184 + 576*33)*4)
__global__ void __launch_bounds__(128) k_conv3(const float* __restrict__ w,
                                               const float* __restrict__ bias)
{
    extern __shared__ float sm[];
    float* s_in = sm;              // 64*81 = 5184
    float* s_w  = sm + 5184;       // [tap(576)][ocl(32)] pitch 33
    const int tb = blockIdx.x, tid = threadIdx.x;
    const int oc_base = blockIdx.y * 32;

    const float4* gin = (const float4*)(g_s2 + tb*5184);
    for (int i = tid; i < 1296; i += 128) ((float4*)s_in)[i] = gin[i];
    const float* wg = w + oc_base*576;
    for (int i = tid; i < 18432; i += 128) {
        int ocl = i / 576, tap = i - ocl*576;
        s_w[tap*33 + ocl] = wg[i];
    }
    __syncthreads();

    int task = tid;   // 100 tasks: 4 oc-groups(8) x 25 pos-groups(2)
    if (task < 100) {
        int ocg = task & 3, posg = task >> 2;
        int oc0 = ocg * 8, p0 = posg * 2;
        float acc[8][2];
        #pragma unroll
        for (int i = 0; i < 8; i++) { acc[i][0] = 0.f; acc[i][1] = 0.f; }
        int base[2];
        #pragma unroll
        for (int j = 0; j < 2; j++) {
            int p = p0 + j; if (p > 48) p = 48;
            int oy = p / 7, ox = p - oy*7;
            base[j] = oy*9 + ox;
        }
        for (int ic = 0; ic < 64; ic++) {
            #pragma unroll
            for (int ky = 0; ky < 3; ky++) {
                int ib = ic*81 + ky*9;
                const float* wrow = s_w + (ic*9 + ky*3)*33 + oc0;
                #pragma unroll
                for (int kx = 0; kx < 3; kx++) {
                    float in0 = s_in[base[0]+ib+kx];
                    float in1 = s_in[base[1]+ib+kx];
                    const float* wp = wrow + kx*33;
                    #pragma unroll
                    for (int i = 0; i < 8; i++) {
                        float wf = wp[i];
                        acc[i][0] += wf*in0; acc[i][1] += wf*in1;
                    }
                }
            }
        }
        #pragma unroll
        for (int i = 0; i < 8; i++) {
            int oc = oc_base + oc0 + i;
            float bb = bias[oc];
            #pragma unroll
            for (int j = 0; j < 2; j++) {
                int p = p0 + j;
                if (p < 49) g_h3[(tb*64 + oc)*49 + p] = acc[i][j] + bb;
            }
        }
    }
}

// ---------------- LIF layer 3 ----------------
__global__ void k_lif3(const float* __restrict__ gamma, const float* __restrict__ beta)
{
    int idx = blockIdx.x*blockDim.x + threadIdx.x;
    if (idx >= 128*3136) return;
    int b = idx / 3136;
    int r = idx - b*3136;
    int c = r / 49;
    float m = g_mean3[c], rs = g_rstd3[c], ga = gamma[c], be = beta[c];
    float v = 0.f;
    #pragma unroll
    for (int t = 0; t < 8; t++) {
        int j = (t*128 + b)*3136 + r;
        float a = (g_h3[j] - m) * rs * ga + be;
        v = v + (a - v)*0.5f;
        float s = (v >= 1.0f) ? 1.0f : 0.0f;
        g_s3[j] = s;
        v = v * (1.0f - s);
    }
}

// ---------------- fc1 GEMM: [1024,3136] x [512,3136]^T -> [1024,512] ----------------
__global__ void __launch_bounds__(256) k_fc1(const float* __restrict__ Wt,
                                             const float* __restrict__ bias)
{
    __shared__ __align__(16) float As[32*68];
    __shared__ __align__(16) float Bs[32*68];
    const int m0 = blockIdx.y * 64, n0 = blockIdx.x * 64;
    const int tid = threadIdx.x;
    const int tx = tid & 15, ty = tid >> 4;
    float acc[4][4];
    #pragma unroll
    for (int i = 0; i < 4; i++)
        #pragma unroll
        for (int j = 0; j < 4; j++) acc[i][j] = 0.f;

    const int lr = tid >> 2;            // 0..63 row within tile
    const int lc = (tid & 3) * 8;       // 0,8,16,24
    const float* Ag = g_s3 + (m0 + lr)*3136 + lc;
    const float* Bg = Wt   + (n0 + lr)*3136 + lc;

    for (int k0 = 0; k0 < 3136; k0 += 32) {
        float4 a0 = *(const float4*)(Ag + k0);
        float4 a1 = *(const float4*)(Ag + k0 + 4);
        float4 b0 = *(const float4*)(Bg + k0);
        float4 b1 = *(const float4*)(Bg + k0 + 4);
        __syncthreads();
        As[(lc+0)*68+lr]=a0.x; As[(lc+1)*68+lr]=a0.y; As[(lc+2)*68+lr]=a0.z; As[(lc+3)*68+lr]=a0.w;
        As[(lc+4)*68+lr]=a1.x; As[(lc+5)*68+lr]=a1.y; As[(lc+6)*68+lr]=a1.z; As[(lc+7)*68+lr]=a1.w;
        Bs[(lc+0)*68+lr]=b0.x; Bs[(lc+1)*68+lr]=b0.y; Bs[(lc+2)*68+lr]=b0.z; Bs[(lc+3)*68+lr]=b0.w;
        Bs[(lc+4)*68+lr]=b1.x; Bs[(lc+5)*68+lr]=b1.y; Bs[(lc+6)*68+lr]=b1.z; Bs[(lc+7)*68+lr]=b1.w;
        __syncthreads();
        #pragma unroll
        for (int kk = 0; kk < 32; kk++) {
            float4 av = *(const float4*)(&As[kk*68 + ty*4]);
            float4 bv = *(const float4*)(&Bs[kk*68 + tx*4]);
            float a[4] = {av.x, av.y, av.z, av.w};
            float b[4] = {bv.x, bv.y, bv.z, bv.w};
            #pragma unroll
            for (int i = 0; i < 4; i++)
                #pragma unroll
                for (int j = 0; j < 4; j++)
                    acc[i][j] += a[i]*b[j];
        }
    }
    #pragma unroll
    for (int i = 0; i < 4; i++) {
        int m = m0 + ty*4 + i;
        #pragma unroll
        for (int j = 0; j < 4; j++) {
            int n = n0 + tx*4 + j;
            g_h4[m*512 + n] = acc[i][j] + bias[n];
        }
    }
}

// ---------------- LIF layer 4 + time-sum of spikes ----------------
__global__ void k_lif4()
{
    int idx = blockIdx.x*blockDim.x + threadIdx.x;
    if (idx >= 128*512) return;
    int b = idx >> 9, o = idx & 511;
    float v = 0.f, cnt = 0.f;
    #pragma unroll
    for (int t = 0; t < 8; t++) {
        float a = g_h4[(t*128 + b)*512 + o];
        v = v + (a - v)*0.5f;
        float s = (v >= 1.0f) ? 1.0f : 0.0f;
        cnt += s;
        v = v * (1.0f - s);
    }
    g_cnt[idx] = cnt;
}

// ---------------- final fco + mean over T ----------------
__global__ void __launch_bounds__(128) k_out(const float* __restrict__ fco_w,
                                             const float* __restrict__ fco_b,
                                             float* __restrict__ out)
{
    int b = blockIdx.x, tid = threadIdx.x;
    float p0 = 0.f, p1 = 0.f;
    for (int o = tid; o < 512; o += 128) {
        float c = g_cnt[b*512 + o];
        p0 += c * fco_w[o];
        p1 += c * fco_w[512 + o];
    }
    __shared__ float s0[128], s1[128];
    s0[tid] = p0; s1[tid] = p1;
    __syncthreads();
    for (int k = 64; k > 0; k >>= 1) {
        if (tid < k) { s0[tid] += s0[tid+k]; s1[tid] += s1[tid+k]; }
        __syncthreads();
    }
    if (tid == 0) {
        out[b*2 + 0] = fco_b[0] + s0[0] * 0.125f;
        out[b*2 + 1] = fco_b[1] + s1[0] * 0.125f;
    }
}

// ---------------- launch ----------------
extern "C" void kernel_launch(void* const* d_in, const int* in_sizes, int n_in,
                              void* d_out, int out_size)
{
    const float* x   = (const float*)d_in[0];
    const float* c1w = (const float*)d_in[1];
    const float* c1b = (const float*)d_in[2];
    const float* g1  = (const float*)d_in[3];
    const float* b1  = (const float*)d_in[4];
    const float* c2w = (const float*)d_in[5];
    const float* c2b = (const float*)d_in[6];
    const float* g2  = (const float*)d_in[7];
    const float* b2  = (const float*)d_in[8];
    const float* c3w = (const float*)d_in[9];
    const float* c3b = (const float*)d_in[10];
    const float* g3  = (const float*)d_in[11];
    const float* b3  = (const float*)d_in[12];
    const float* fw  = (const float*)d_in[13];
    const float* fb  = (const float*)d_in[14];
    const float* ow  = (const float*)d_in[15];
    const float* ob  = (const float*)d_in[16];
    float* out = (float*)d_out;

    cudaFuncSetAttribute(k_conv1, cudaFuncAttributeMaxDynamicSharedMemorySize, SMEM1);
    cudaFuncSetAttribute(k_conv2, cudaFuncAttributeMaxDynamicSharedMemorySize, SMEM2);
    cudaFuncSetAttribute(k_conv3, cudaFuncAttributeMaxDynamicSharedMemorySize, SMEM3);

    k_conv1<<<128, 256, SMEM1>>>(x, c1w, c1b);
    k_bnstats<<<32, 256>>>(0, 128, 32, 400);
    k_lif1<<<(1638400 + 255)/256, 256>>>(g1, b1);

    k_conv2<<<1024, 256, SMEM2>>>(c2w, c2b);
    k_bnstats<<<64, 256>>>(1, 1024, 64, 81);
    k_lif2<<<(663552 + 255)/256, 256>>>(g2, b2);

    k_conv3<<<dim3(1024, 2), 128, SMEM3>>>(c3w, c3b);
    k_bnstats<<<64, 256>>>(2, 1024, 64, 49);
    k_lif3<<<(401408 + 255)/256, 256>>>(g3, b3);

    k_fc1<<<dim3(8, 16), 256>>>(fw, fb);
    k_lif4<<<256, 256>>>();
    k_out<<<128, 128>>>(ow, ob, out);
}

// round 7
// speedup vs baseline: 2.5732x; 2.5732x over previous
#include <cuda_runtime.h>
#include <cuda_bf16.h>
#include <cstdint>

// ================= scratch (device globals; no allocation allowed) =================
__device__ __align__(16) float g_h1[128*32*400];                  // conv1 out (1 timestep)
__device__ __align__(16) __nv_bfloat16 g_s1b[8*128*32*400];       // spikes L1 bf16
__device__ __align__(16) __nv_bfloat16 g_A2[82944*512];           // im2col for conv2
__device__ __align__(16) float g_h2[82944*64];                    // conv2 out [M][oc]
__device__ __align__(16) __nv_bfloat16 g_s2b[8*128*64*81];        // spikes L2 bf16 [tb][c][pos]
__device__ __align__(16) __nv_bfloat16 g_A3[50176*576];           // im2col for conv3
__device__ __align__(16) float g_h3[50176*64];                    // conv3 out [M][oc]
__device__ __align__(16) __nv_bfloat16 g_A4[1024*3136];           // spikes L3 flat bf16
__device__ __align__(16) float g_h4[1024*512];                    // fc1 out
__device__ __align__(16) float g_cnt[128*512];
__device__ float g_mean1[32], g_rstd1[32];
__device__ float g_mean2[64], g_rstd2[64];
__device__ float g_mean3[64], g_rstd3[64];
__device__ float g_bnacc[256];   // [sum2(64) | sq2(64) | sum3(64) | sq3(64)]
__device__ __align__(16) __nv_bfloat16 g_w2hi[64*512],  g_w2lo[64*512];
__device__ __align__(16) __nv_bfloat16 g_w3hi[64*576],  g_w3lo[64*576];
__device__ __align__(16) __nv_bfloat16 g_wfhi[512*3136], g_wflo[512*3136];

// ================= conv1 (fp32): [128,4,84,84] -> [128,32,20,20] =================
#define SMEM1 ((28224 + 256*33)*4)
__global__ void __launch_bounds__(256) k_conv1(const float* __restrict__ x,
                                               const float* __restrict__ w,
                                               const float* __restrict__ bias)
{
    extern __shared__ float sm[];
    float* s_in = sm;
    float* s_w  = sm + 28224;
    const int n = blockIdx.x, tid = threadIdx.x;

    const float4* gx = (const float4*)(x + n*28224);
    for (int i = tid; i < 7056; i += 256) ((float4*)s_in)[i] = gx[i];
    for (int i = tid; i < 8192; i += 256) {
        int oc = i >> 8, tap = i & 255;
        s_w[tap*33 + oc] = w[i];
    }
    __syncthreads();

    for (int task = tid; task < 400; task += 256) {
        int ocg = task & 3, posg = task >> 2;
        int oc0 = ocg * 8, p0 = posg * 4;
        float acc[8][4];
        #pragma unroll
        for (int i = 0; i < 8; i++)
            #pragma unroll
            for (int j = 0; j < 4; j++) acc[i][j] = 0.f;
        int base[4];
        #pragma unroll
        for (int j = 0; j < 4; j++) {
            int p = p0 + j, oy = p / 20, ox = p - oy*20;
            base[j] = oy*4*84 + ox*4;
        }
        for (int ic = 0; ic < 4; ic++) {
            #pragma unroll
            for (int ky = 0; ky < 8; ky++) {
                int ib = ic*7056 + ky*84;
                const float* wrow = s_w + (ic*64 + ky*8)*33 + oc0;
                #pragma unroll
                for (int kx = 0; kx < 8; kx++) {
                    float in0 = s_in[base[0]+ib+kx];
                    float in1 = s_in[base[1]+ib+kx];
                    float in2 = s_in[base[2]+ib+kx];
                    float in3 = s_in[base[3]+ib+kx];
                    const float* wp = wrow + kx*33;
                    #pragma unroll
                    for (int i = 0; i < 8; i++) {
                        float wf = wp[i];
                        acc[i][0] += wf*in0; acc[i][1] += wf*in1;
                        acc[i][2] += wf*in2; acc[i][3] += wf*in3;
                    }
                }
            }
        }
        #pragma unroll
        for (int i = 0; i < 8; i++) {
            float bb = bias[oc0+i];
            #pragma unroll
            for (int j = 0; j < 4; j++)
                g_h1[(n*32 + oc0+i)*400 + p0 + j] = acc[i][j] + bb;
        }
    }
}

// ================= BN stats layer 1 (layout [n][c][400]) =================
__global__ void __launch_bounds__(256) k_bnstats1()
{
    int c = blockIdx.x, tid = threadIdx.x;
    float sum = 0.f, sq = 0.f;
    for (int i = tid; i < 128*400; i += 256) {
        int n = i / 400, s = i - n*400;
        float v = g_h1[(n*32 + c)*400 + s];
        sum += v; sq += v*v;
    }
    __shared__ float ss[512];
    ss[tid] = sum; ss[256+tid] = sq;
    __syncthreads();
    for (int k = 128; k > 0; k >>= 1) {
        if (tid < k) { ss[tid] += ss[tid+k]; ss[256+tid] += ss[256+tid+k]; }
        __syncthreads();
    }
    if (tid == 0) {
        float m = ss[0] / 51200.f;
        float var = ss[256] / 51200.f - m*m;
        g_mean1[c] = m;
        g_rstd1[c] = rsqrtf(var + 1e-5f);
    }
}

// ================= LIF layer 1 -> bf16 spikes =================
__global__ void k_lif1(const float* __restrict__ gamma, const float* __restrict__ beta)
{
    int idx = blockIdx.x*blockDim.x + threadIdx.x;
    if (idx >= 128*32*400) return;
    int c = (idx / 400) & 31;
    float a = (g_h1[idx] - g_mean1[c]) * g_rstd1[c] * gamma[c] + beta[c];
    float v = 0.f;
    #pragma unroll
    for (int t = 0; t < 8; t++) {
        v = v + (a - v)*0.5f;
        float s = (v >= 1.0f) ? 1.0f : 0.0f;
        g_s1b[t*1638400 + idx] = __float2bfloat16(s);
        v = v * (1.0f - s);
    }
}

// ================= im2col for conv2: -> A2[tb*81+pos][ (ky*4+kx)*32 + c ] =================
__global__ void __launch_bounds__(256) k_im2col2()
{
    __shared__ __align__(16) __nv_bfloat16 s_t[32*402];
    int tb = blockIdx.x;
    int t = tb >> 7, b = tb & 127;
    const uint32_t* src = (const uint32_t*)(g_s1b + (size_t)t*1638400 + (size_t)b*12800);
    for (int i = threadIdx.x; i < 6400; i += 256) {
        int c = i / 200, s = i - c*200;
        ((uint32_t*)(s_t + c*402))[s] = src[c*200 + s];
    }
    __syncthreads();
    for (int task = threadIdx.x; task < 2592; task += 256) {
        int pos = task >> 5, c = task & 31;
        int oy = pos / 9, ox = pos - oy*9;
        const __nv_bfloat16* w = s_t + c*402 + oy*40 + ox*2;
        __nv_bfloat16* dst = g_A2 + (size_t)(tb*81 + pos)*512 + c;
        #pragma unroll
        for (int ky = 0; ky < 4; ky++)
            #pragma unroll
            for (int kx = 0; kx < 4; kx++)
                dst[(ky*4+kx)*32] = w[ky*20 + kx];
    }
}

// ================= weight split: W -> (hi, lo) bf16, permute tap to [ky][kx][ic] =================
template<int SEL>
__global__ void k_wsplit(const float* __restrict__ src)
{
    constexpr int OC  = (SEL == 0) ? 64 : (SEL == 1) ? 64 : 512;
    constexpr int IC  = (SEL == 0) ? 32 : (SEL == 1) ? 64 : 3136;
    constexpr int KHW = (SEL == 0) ? 16 : (SEL == 1) ? 9  : 1;
    constexpr int K = IC*KHW;
    __nv_bfloat16* hi = (SEL == 0) ? g_w2hi : (SEL == 1) ? g_w3hi : g_wfhi;
    __nv_bfloat16* lo = (SEL == 0) ? g_w2lo : (SEL == 1) ? g_w3lo : g_wflo;
    int idx = blockIdx.x*256 + threadIdx.x;
    if (idx >= OC*K) return;
    int oc = idx / K, rem = idx - oc*K;
    int ic = rem / KHW, kk = rem - ic*KHW;
    int tap = kk*IC + ic;
    float w = src[idx];
    __nv_bfloat16 h = __float2bfloat16(w);
    float hf = __bfloat162float(h);
    hi[oc*K + tap] = h;
    lo[oc*K + tap] = __float2bfloat16(w - hf);
}

__global__ void k_zero()
{
    if (threadIdx.x < 256) g_bnacc[threadIdx.x] = 0.f;
}

// ================= bf16 mma.sync GEMM: C[M][Ntot] = A[M][K]*(Bhi+Blo)[Ntot][K]^T + bias ==========
// block tile 128x64, 8 warps (4m x 2n), warp tile 32x32, K-chunk 32.
// mma.sync.aligned.m16n8k16.row.col.f32.bf16.bf16.f32 (sm_80+, legacy HMMA pipe).
#define MMA_OP(d, a0,a1,a2,a3, b0,b1) \
    asm volatile("mma.sync.aligned.m16n8k16.row.col.f32.bf16.bf16.f32 " \
        "{%0,%1,%2,%3}, {%4,%5,%6,%7}, {%8,%9}, {%0,%1,%2,%3};" \
        : "+f"((d)[0]), "+f"((d)[1]), "+f"((d)[2]), "+f"((d)[3]) \
        : "r"(a0), "r"(a1), "r"(a2), "r"(a3), "r"(b0), "r"(b1))

template<int LAYER>
__global__ void __launch_bounds__(256) k_gemm(const float* __restrict__ bias)
{
    constexpr int K    = (LAYER == 0) ? 512 : (LAYER == 1) ? 576 : 3136;
    constexpr int NTOT = (LAYER == 2) ? 512 : 64;
    const __nv_bfloat16* A   = (LAYER == 0) ? g_A2  : (LAYER == 1) ? g_A3  : g_A4;
    const __nv_bfloat16* Bhi = (LAYER == 0) ? g_w2hi: (LAYER == 1) ? g_w3hi: g_wfhi;
    const __nv_bfloat16* Blo = (LAYER == 0) ? g_w2lo: (LAYER == 1) ? g_w3lo: g_wflo;
    float* C                 = (LAYER == 0) ? g_h2  : (LAYER == 1) ? g_h3  : g_h4;

    __shared__ __align__(16) __nv_bfloat16 sA[128*40];   // chunk 32k, pitch 40
    __shared__ __align__(16) __nv_bfloat16 sBh[64*40];
    __shared__ __align__(16) __nv_bfloat16 sBl[64*40];

    const int tid = threadIdx.x;
    const int wid = tid >> 5, lane = tid & 31;
    const int gq = lane >> 2, q = lane & 3;      // fragment row-group / quad
    const int wm = wid & 3, wn = wid >> 2;       // warp grid 4(m) x 2(n)
    const int m0 = blockIdx.x * 128, n0 = blockIdx.y * 64;

    float acc[2][4][4];
    #pragma unroll
    for (int mi = 0; mi < 2; mi++)
        #pragma unroll
        for (int nt = 0; nt < 4; nt++)
            #pragma unroll
            for (int j = 0; j < 4; j++) acc[mi][nt][j] = 0.f;

    constexpr int nchunk = K >> 5;
    for (int c = 0; c < nchunk; c++) {
        int k0 = c << 5;
        __syncthreads();
        // A: 128 rows x 32 bf16 = 512 uint4
        #pragma unroll
        for (int it = 0; it < 2; it++) {
            int i = tid + it*256;
            int r = i >> 2, gg = i & 3;
            *(uint4*)(sA + r*40 + gg*8) = *(const uint4*)(A + (size_t)(m0 + r)*K + k0 + gg*8);
        }
        // B hi/lo: 64 rows x 32 bf16 each = 256 uint4 each
        {
            int r = tid >> 2, gg = tid & 3;
            *(uint4*)(sBh + r*40 + gg*8) = *(const uint4*)(Bhi + (size_t)(n0 + r)*K + k0 + gg*8);
            *(uint4*)(sBl + r*40 + gg*8) = *(const uint4*)(Blo + (size_t)(n0 + r)*K + k0 + gg*8);
        }
        __syncthreads();

        const uint32_t* wA  = (const uint32_t*)sA;
        const uint32_t* wBh = (const uint32_t*)sBh;
        const uint32_t* wBl = (const uint32_t*)sBl;
        #pragma unroll
        for (int ks = 0; ks < 2; ks++) {
            int kw = ks * 8;   // word offset within 20-word row
            uint32_t a[2][4];
            #pragma unroll
            for (int mi = 0; mi < 2; mi++) {
                int r0 = wm*32 + mi*16 + gq;
                a[mi][0] = wA[r0*20 + kw + q];
                a[mi][1] = wA[(r0+8)*20 + kw + q];
                a[mi][2] = wA[r0*20 + kw + 4 + q];
                a[mi][3] = wA[(r0+8)*20 + kw + 4 + q];
            }
            #pragma unroll
            for (int nt = 0; nt < 4; nt++) {
                int n = wn*32 + nt*8 + gq;
                uint32_t bh0 = wBh[n*20 + kw + q];
                uint32_t bh1 = wBh[n*20 + kw + 4 + q];
                MMA_OP(acc[0][nt], a[0][0],a[0][1],a[0][2],a[0][3], bh0, bh1);
                MMA_OP(acc[1][nt], a[1][0],a[1][1],a[1][2],a[1][3], bh0, bh1);
                uint32_t bl0 = wBl[n*20 + kw + q];
                uint32_t bl1 = wBl[n*20 + kw + 4 + q];
                MMA_OP(acc[0][nt], a[0][0],a[0][1],a[0][2],a[0][3], bl0, bl1);
                MMA_OP(acc[1][nt], a[1][0],a[1][1],a[1][2],a[1][3], bl0, bl1);
            }
        }
    }

    // epilogue: c0,c1 -> row gq; c2,c3 -> row gq+8; cols q*2, q*2+1
    #pragma unroll
    for (int mi = 0; mi < 2; mi++) {
        int r0 = m0 + wm*32 + mi*16 + gq;
        #pragma unroll
        for (int nt = 0; nt < 4; nt++) {
            int n = n0 + wn*32 + nt*8 + q*2;
            float b0 = bias[n], b1 = bias[n+1];
            float2 v0; v0.x = acc[mi][nt][0] + b0; v0.y = acc[mi][nt][1] + b1;
            float2 v1; v1.x = acc[mi][nt][2] + b0; v1.y = acc[mi][nt][3] + b1;
            *(float2*)(C + (size_t)r0*NTOT + n) = v0;
            *(float2*)(C + (size_t)(r0+8)*NTOT + n) = v1;
        }
    }
}

// ================= BN gather (layout [rows][64]) + finalize =================
template<int SEL>
__global__ void __launch_bounds__(256) k_bngather()
{
    const float* h = (SEL == 0) ? g_h2 : g_h3;
    constexpr int rows = (SEL == 0) ? 82944 : 50176;
    float* sum = (SEL == 0) ? g_bnacc       : g_bnacc + 128;
    float* sq  = (SEL == 0) ? g_bnacc + 64  : g_bnacc + 192;
    int gw = blockIdx.x*8 + (threadIdx.x >> 5);
    int lid = threadIdx.x & 31;
    int W = gridDim.x * 8;
    float s0 = 0.f, q0 = 0.f, s1 = 0.f, q1 = 0.f;
    for (int r = gw; r < rows; r += W) {
        float a = h[(size_t)r*64 + lid];
        float b = h[(size_t)r*64 + 32 + lid];
        s0 += a; q0 += a*a; s1 += b; q1 += b*b;
    }
    atomicAdd(&sum[lid], s0);      atomicAdd(&sq[lid], q0);
    atomicAdd(&sum[32+lid], s1);   atomicAdd(&sq[32+lid], q1);
}

template<int SEL>
__global__ void k_bnfin()
{
    const float* sum = (SEL == 0) ? g_bnacc      : g_bnacc + 128;
    const float* sq  = (SEL == 0) ? g_bnacc + 64 : g_bnacc + 192;
    float* mean = (SEL == 0) ? g_mean2 : g_mean3;
    float* rstd = (SEL == 0) ? g_rstd2 : g_rstd3;
    constexpr float invn = (SEL == 0) ? (1.f/82944.f) : (1.f/50176.f);
    int c = threadIdx.x;
    if (c >= 64) return;
    float m = sum[c] * invn;
    float v = sq[c] * invn - m*m;
    mean[c] = m;
    rstd[c] = rsqrtf(v + 1e-5f);
}

// ================= LIF layer 2: h2[(tb*81+pos)*64+c] -> s2b[(tb*64+c)*81+pos] =================
__global__ void k_lif2(const float* __restrict__ gamma, const float* __restrict__ beta)
{
    int idx = blockIdx.x*blockDim.x + threadIdx.x;
    if (idx >= 128*81*64) return;
    int c = idx & 63;
    int bp = idx >> 6;
    int b = bp / 81, pos = bp - b*81;
    float m = g_mean2[c];
    float sc = g_rstd2[c]*gamma[c];
    float be = beta[c];
    float v = 0.f;
    #pragma unroll
    for (int t = 0; t < 8; t++) {
        int tb = t*128 + b;
        float a = (g_h2[(size_t)(tb*81 + pos)*64 + c] - m)*sc + be;
        v = v + (a - v)*0.5f;
        float s = (v >= 1.0f) ? 1.0f : 0.0f;
        g_s2b[(size_t)(tb*64 + c)*81 + pos] = __float2bfloat16(s);
        v = v * (1.0f - s);
    }
}

// ================= im2col for conv3: -> A3[tb*49+pos][ (ky*3+kx)*64 + c ] =================
__global__ void __launch_bounds__(256) k_im2col3()
{
    __shared__ __nv_bfloat16 s_t[64*83];
    int tb = blockIdx.x;
    const __nv_bfloat16* src = g_s2b + (size_t)tb*5184;
    for (int i = threadIdx.x; i < 5184; i += 256) {
        int c = i / 81, p = i - c*81;
        s_t[c*83 + p] = src[i];
    }
    __syncthreads();
    for (int task = threadIdx.x; task < 3136; task += 256) {
        int pos = task >> 6, c = task & 63;
        int oy = pos / 7, ox = pos - oy*7;
        const __nv_bfloat16* w = s_t + c*83 + oy*9 + ox;
        __nv_bfloat16* dst = g_A3 + (size_t)(tb*49 + pos)*576 + c;
        #pragma unroll
        for (int ky = 0; ky < 3; ky++)
            #pragma unroll
            for (int kx = 0; kx < 3; kx++)
                dst[(ky*3+kx)*64] = w[ky*9 + kx];
    }
}

// ================= LIF layer 3: h3[(tb*49+pos)*64+c] -> A4[tb*3136 + c*49+pos] =================
__global__ void k_lif3(const float* __restrict__ gamma, const float* __restrict__ beta)
{
    int idx = blockIdx.x*blockDim.x + threadIdx.x;
    if (idx >= 128*49*64) return;
    int c = idx & 63;
    int bp = idx >> 6;
    int b = bp / 49, pos = bp - b*49;
    float m = g_mean3[c];
    float sc = g_rstd3[c]*gamma[c];
    float be = beta[c];
    float v = 0.f;
    #pragma unroll
    for (int t = 0; t < 8; t++) {
        int tb = t*128 + b;
        float a = (g_h3[(size_t)(tb*49 + pos)*64 + c] - m)*sc + be;
        v = v + (a - v)*0.5f;
        float s = (v >= 1.0f) ? 1.0f : 0.0f;
        g_A4[(size_t)tb*3136 + c*49 + pos] = __float2bfloat16(s);
        v = v * (1.0f - s);
    }
}

// ================= LIF layer 4 + spike counts =================
__global__ void k_lif4()
{
    int idx = blockIdx.x*blockDim.x + threadIdx.x;
    if (idx >= 128*512) return;
    int b = idx >> 9, o = idx & 511;
    float v = 0.f, cnt = 0.f;
    #pragma unroll
    for (int t = 0; t < 8; t++) {
        float a = g_h4[(t*128 + b)*512 + o];
        v = v + (a - v)*0.5f;
        float s = (v >= 1.0f) ? 1.0f : 0.0f;
        cnt += s;
        v = v * (1.0f - s);
    }
    g_cnt[idx] = cnt;
}

// ================= final fco + mean over T =================
__global__ void __launch_bounds__(128) k_out(const float* __restrict__ fco_w,
                                             const float* __restrict__ fco_b,
                                             float* __restrict__ out)
{
    int b = blockIdx.x, tid = threadIdx.x;
    float p0 = 0.f, p1 = 0.f;
    for (int o = tid; o < 512; o += 128) {
        float c = g_cnt[b*512 + o];
        p0 += c * fco_w[o];
        p1 += c * fco_w[512 + o];
    }
    __shared__ float s0[128], s1[128];
    s0[tid] = p0; s1[tid] = p1;
    __syncthreads();
    for (int k = 64; k > 0; k >>= 1) {
        if (tid < k) { s0[tid] += s0[tid+k]; s1[tid] += s1[tid+k]; }
        __syncthreads();
    }
    if (tid == 0) {
        out[b*2 + 0] = fco_b[0] + s0[0] * 0.125f;
        out[b*2 + 1] = fco_b[1] + s1[0] * 0.125f;
    }
}

// ================= launch =================
extern "C" void kernel_launch(void* const* d_in, const int* in_sizes, int n_in,
                              void* d_out, int out_size)
{
    const float* x   = (const float*)d_in[0];
    const float* c1w = (const float*)d_in[1];
    const float* c1b = (const float*)d_in[2];
    const float* g1  = (const float*)d_in[3];
    const float* b1  = (const float*)d_in[4];
    const float* c2w = (const float*)d_in[5];
    const float* c2b = (const float*)d_in[6];
    const float* g2  = (const float*)d_in[7];
    const float* b2  = (const float*)d_in[8];
    const float* c3w = (const float*)d_in[9];
    const float* c3b = (const float*)d_in[10];
    const float* g3  = (const float*)d_in[11];
    const float* b3  = (const float*)d_in[12];
    const float* fw  = (const float*)d_in[13];
    const float* fb  = (const float*)d_in[14];
    const float* ow  = (const float*)d_in[15];
    const float* ob  = (const float*)d_in[16];
    float* out = (float*)d_out;

    cudaFuncSetAttribute(k_conv1, cudaFuncAttributeMaxDynamicSharedMemorySize, SMEM1);

    k_zero<<<1, 256>>>();
    k_wsplit<0><<<(64*512 + 255)/256, 256>>>(c2w);
    k_wsplit<1><<<(64*576 + 255)/256, 256>>>(c3w);
    k_wsplit<2><<<(512*3136 + 255)/256, 256>>>(fw);

    k_conv1<<<128, 256, SMEM1>>>(x, c1w, c1b);
    k_bnstats1<<<32, 256>>>();
    k_lif1<<<(1638400 + 255)/256, 256>>>(g1, b1);

    k_im2col2<<<1024, 256>>>();
    k_gemm<0><<<dim3(648, 1), 256>>>(c2b);
    k_bngather<0><<<256, 256>>>();
    k_bnfin<0><<<1, 64>>>();
    k_lif2<<<(663552 + 255)/256, 256>>>(g2, b2);

    k_im2col3<<<1024, 256>>>();
    k_gemm<1><<<dim3(392, 1), 256>>>(c3b);
    k_bngather<1><<<128, 256>>>();
    k_bnfin<1><<<1, 64>>>();
    k_lif3<<<(401408 + 255)/256, 256>>>(g3, b3);

    k_gemm<2><<<dim3(8, 8), 256>>>(fb);
    k_lif4<<<256, 256>>>();
    k_out<<<128, 128>>>(ow, ob, out);
}

// round 8
// speedup vs baseline: 4.2016x; 1.6328x over previous
#include <cuda_runtime.h>
#include <cuda_bf16.h>
#include <cstdint>

// ================= scratch (device globals; no allocation allowed) =================
__device__ __align__(16) float g_h1[128*32*400];                  // conv1 out (1 timestep)
__device__ __align__(16) __nv_bfloat16 g_s1b[8*128*32*400];       // spikes L1 bf16
__device__ __align__(16) __nv_bfloat16 g_A2[82944*512];           // im2col for conv2
__device__ __align__(16) float g_h2[82944*64];                    // conv2 out [M][oc]
__device__ __align__(16) __nv_bfloat16 g_s2b[8*128*81*64];        // spikes L2 bf16 [tb][pos][c]
__device__ __align__(16) __nv_bfloat16 g_A3[50176*576];           // im2col for conv3
__device__ __align__(16) float g_h3[50176*64];                    // conv3 out [M][oc]
__device__ __align__(16) __nv_bfloat16 g_A4[1024*3136];           // spikes L3 flat bf16
__device__ __align__(16) float g_h4[2*1024*512];                  // fc1 out (2 K-split partials)
__device__ __align__(16) float g_cnt[128*512];
__device__ float g_mean1[32], g_rstd1[32];
__device__ float g_mean2[64], g_rstd2[64];
__device__ float g_mean3[64], g_rstd3[64];
__device__ float g_bnacc[256];   // [sum2(64) | sq2(64) | sum3(64) | sq3(64)]
__device__ __align__(16) __nv_bfloat16 g_w2hi[64*512],  g_w2lo[64*512];
__device__ __align__(16) __nv_bfloat16 g_w3hi[64*576],  g_w3lo[64*576];
__device__ __align__(16) __nv_bfloat16 g_wfhi[512*3136], g_wflo[512*3136];

// ================= helpers =================
__device__ __forceinline__ uint32_t smem_u32(const void* p) {
    return (uint32_t)__cvta_generic_to_shared(p);
}
#define CP16(dst_u32, src_ptr) \
    asm volatile("cp.async.cg.shared.global [%0], [%1], 16;" :: "r"(dst_u32), "l"(src_ptr))
#define CP_COMMIT() asm volatile("cp.async.commit_group;" ::: "memory")
#define CP_WAIT(n)  asm volatile("cp.async.wait_group %0;" :: "n"(n) : "memory")

// ================= conv1 (fp32): [128,4,84,84] -> [128,32,20,20] =================
#define SMEM1 ((28224 + 256*33)*4)
__global__ void __launch_bounds__(256) k_conv1(const float* __restrict__ x,
                                               const float* __restrict__ w,
                                               const float* __restrict__ bias)
{
    extern __shared__ float sm[];
    float* s_in = sm;
    float* s_w  = sm + 28224;
    const int n = blockIdx.x, tid = threadIdx.x;

    const float4* gx = (const float4*)(x + n*28224);
    for (int i = tid; i < 7056; i += 256) ((float4*)s_in)[i] = gx[i];
    for (int i = tid; i < 8192; i += 256) {
        int oc = i >> 8, tap = i & 255;
        s_w[tap*33 + oc] = w[i];
    }
    __syncthreads();

    for (int task = tid; task < 400; task += 256) {
        int ocg = task & 3, posg = task >> 2;
        int oc0 = ocg * 8, p0 = posg * 4;
        float acc[8][4];
        #pragma unroll
        for (int i = 0; i < 8; i++)
            #pragma unroll
            for (int j = 0; j < 4; j++) acc[i][j] = 0.f;
        int base[4];
        #pragma unroll
        for (int j = 0; j < 4; j++) {
            int p = p0 + j, oy = p / 20, ox = p - oy*20;
            base[j] = oy*4*84 + ox*4;
        }
        for (int ic = 0; ic < 4; ic++) {
            #pragma unroll
            for (int ky = 0; ky < 8; ky++) {
                int ib = ic*7056 + ky*84;
                const float* wrow = s_w + (ic*64 + ky*8)*33 + oc0;
                #pragma unroll
                for (int kx = 0; kx < 8; kx++) {
                    float in0 = s_in[base[0]+ib+kx];
                    float in1 = s_in[base[1]+ib+kx];
                    float in2 = s_in[base[2]+ib+kx];
                    float in3 = s_in[base[3]+ib+kx];
                    const float* wp = wrow + kx*33;
                    #pragma unroll
                    for (int i = 0; i < 8; i++) {
                        float wf = wp[i];
                        acc[i][0] += wf*in0; acc[i][1] += wf*in1;
                        acc[i][2] += wf*in2; acc[i][3] += wf*in3;
                    }
                }
            }
        }
        #pragma unroll
        for (int i = 0; i < 8; i++) {
            float bb = bias[oc0+i];
            #pragma unroll
            for (int j = 0; j < 4; j++)
                g_h1[(n*32 + oc0+i)*400 + p0 + j] = acc[i][j] + bb;
        }
    }
}

// ================= BN stats layer 1 (layout [n][c][400]) =================
__global__ void __launch_bounds__(256) k_bnstats1()
{
    int c = blockIdx.x, tid = threadIdx.x;
    float sum = 0.f, sq = 0.f;
    for (int i = tid; i < 128*400; i += 256) {
        int n = i / 400, s = i - n*400;
        float v = g_h1[(n*32 + c)*400 + s];
        sum += v; sq += v*v;
    }
    __shared__ float ss[512];
    ss[tid] = sum; ss[256+tid] = sq;
    __syncthreads();
    for (int k = 128; k > 0; k >>= 1) {
        if (tid < k) { ss[tid] += ss[tid+k]; ss[256+tid] += ss[256+tid+k]; }
        __syncthreads();
    }
    if (tid == 0) {
        float m = ss[0] / 51200.f;
        float var = ss[256] / 51200.f - m*m;
        g_mean1[c] = m;
        g_rstd1[c] = rsqrtf(var + 1e-5f);
    }
}

// ================= LIF layer 1 -> bf16 spikes =================
__global__ void k_lif1(const float* __restrict__ gamma, const float* __restrict__ beta)
{
    int idx = blockIdx.x*blockDim.x + threadIdx.x;
    if (idx >= 128*32*400) return;
    int c = (idx / 400) & 31;
    float a = (g_h1[idx] - g_mean1[c]) * g_rstd1[c] * gamma[c] + beta[c];
    float v = 0.f;
    #pragma unroll
    for (int t = 0; t < 8; t++) {
        v = v + (a - v)*0.5f;
        float s = (v >= 1.0f) ? 1.0f : 0.0f;
        g_s1b[t*1638400 + idx] = __float2bfloat16(s);
        v = v * (1.0f - s);
    }
}

// ================= im2col for conv2: -> A2[tb*81+pos][ (ky*4+kx)*32 + c ] =================
__global__ void __launch_bounds__(256) k_im2col2()
{
    __shared__ __align__(16) __nv_bfloat16 s_t[32*402];
    int tb = blockIdx.x;
    int t = tb >> 7, b = tb & 127;
    const uint32_t* src = (const uint32_t*)(g_s1b + (size_t)t*1638400 + (size_t)b*12800);
    for (int i = threadIdx.x; i < 6400; i += 256) {
        int c = i / 200, s = i - c*200;
        ((uint32_t*)(s_t + c*402))[s] = src[c*200 + s];
    }
    __syncthreads();
    for (int task = threadIdx.x; task < 2592; task += 256) {
        int pos = task >> 5, c = task & 31;
        int oy = pos / 9, ox = pos - oy*9;
        const __nv_bfloat16* w = s_t + c*402 + oy*40 + ox*2;
        __nv_bfloat16* dst = g_A2 + (size_t)(tb*81 + pos)*512 + c;
        #pragma unroll
        for (int ky = 0; ky < 4; ky++)
            #pragma unroll
            for (int kx = 0; kx < 4; kx++)
                dst[(ky*4+kx)*32] = w[ky*20 + kx];
    }
}

// ================= weight split: W -> (hi, lo) bf16, permute tap to [ky][kx][ic] =================
template<int SEL>
__global__ void k_wsplit(const float* __restrict__ src)
{
    constexpr int OC  = (SEL == 0) ? 64 : (SEL == 1) ? 64 : 512;
    constexpr int IC  = (SEL == 0) ? 32 : (SEL == 1) ? 64 : 3136;
    constexpr int KHW = (SEL == 0) ? 16 : (SEL == 1) ? 9  : 1;
    constexpr int K = IC*KHW;
    __nv_bfloat16* hi = (SEL == 0) ? g_w2hi : (SEL == 1) ? g_w3hi : g_wfhi;
    __nv_bfloat16* lo = (SEL == 0) ? g_w2lo : (SEL == 1) ? g_w3lo : g_wflo;
    int idx = blockIdx.x*256 + threadIdx.x;
    if (idx >= OC*K) return;
    int oc = idx / K, rem = idx - oc*K;
    int ic = rem / KHW, kk = rem - ic*KHW;
    int tap = kk*IC + ic;
    float w = src[idx];
    __nv_bfloat16 h = __float2bfloat16(w);
    float hf = __bfloat162float(h);
    hi[oc*K + tap] = h;
    lo[oc*K + tap] = __float2bfloat16(w - hf);
}

__global__ void k_zero()
{
    if (threadIdx.x < 256) g_bnacc[threadIdx.x] = 0.f;
}

// ================= bf16 mma.sync GEMM, cp.async double-buffered ==========
// block tile 128x64, 8 warps (4m x 2n), warp tile 32x32, K-chunk 32.
#define MMA_OP(d, a0,a1,a2,a3, b0,b1) \
    asm volatile("mma.sync.aligned.m16n8k16.row.col.f32.bf16.bf16.f32 " \
        "{%0,%1,%2,%3}, {%4,%5,%6,%7}, {%8,%9}, {%0,%1,%2,%3};" \
        : "+f"((d)[0]), "+f"((d)[1]), "+f"((d)[2]), "+f"((d)[3]) \
        : "r"(a0), "r"(a1), "r"(a2), "r"(a3), "r"(b0), "r"(b1))

template<int LAYER>
__global__ void __launch_bounds__(256) k_gemm(const float* __restrict__ bias)
{
    constexpr int K    = (LAYER == 0) ? 512 : (LAYER == 1) ? 576 : 3136;
    constexpr int NTOT = (LAYER == 2) ? 512 : 64;
    constexpr int NCH  = (LAYER == 0) ? 16 : (LAYER == 1) ? 18 : 49;  // chunks per block
    const __nv_bfloat16* A   = (LAYER == 0) ? g_A2  : (LAYER == 1) ? g_A3  : g_A4;
    const __nv_bfloat16* Bhi = (LAYER == 0) ? g_w2hi: (LAYER == 1) ? g_w3hi: g_wfhi;
    const __nv_bfloat16* Blo = (LAYER == 0) ? g_w2lo: (LAYER == 1) ? g_w3lo: g_wflo;
    float* C                 = (LAYER == 0) ? g_h2  : (LAYER == 1) ? g_h3
                                            : g_h4 + (size_t)blockIdx.z*524288;
    const int cbase = (LAYER == 2) ? blockIdx.z*49 : 0;

    __shared__ __align__(16) __nv_bfloat16 sA[2][128*40];
    __shared__ __align__(16) __nv_bfloat16 sBh[2][64*40];
    __shared__ __align__(16) __nv_bfloat16 sBl[2][64*40];

    const int tid = threadIdx.x;
    const int wid = tid >> 5, lane = tid & 31;
    const int gq = lane >> 2, q = lane & 3;
    const int wm = wid & 3, wn = wid >> 2;
    const int m0 = blockIdx.x * 128, n0 = blockIdx.y * 64;

    uint32_t uA[2]  = { smem_u32(sA[0]),  smem_u32(sA[1]) };
    uint32_t uBh[2] = { smem_u32(sBh[0]), smem_u32(sBh[1]) };
    uint32_t uBl[2] = { smem_u32(sBl[0]), smem_u32(sBl[1]) };

    auto load_chunk = [&](int cc, int buf) {
        int k0 = (cbase + cc) << 5;
        #pragma unroll
        for (int it = 0; it < 2; it++) {
            int i = tid + it*256;
            int r = i >> 2, gg = i & 3;
            CP16(uA[buf] + (uint32_t)(r*40 + gg*8)*2,
                 A + (size_t)(m0 + r)*K + k0 + gg*8);
        }
        int r = tid >> 2, gg = tid & 3;
        CP16(uBh[buf] + (uint32_t)(r*40 + gg*8)*2,
             Bhi + (size_t)(n0 + r)*K + k0 + gg*8);
        CP16(uBl[buf] + (uint32_t)(r*40 + gg*8)*2,
             Blo + (size_t)(n0 + r)*K + k0 + gg*8);
    };

    float acc[2][4][4];
    #pragma unroll
    for (int mi = 0; mi < 2; mi++)
        #pragma unroll
        for (int nt = 0; nt < 4; nt++)
            #pragma unroll
            for (int j = 0; j < 4; j++) acc[mi][nt][j] = 0.f;

    load_chunk(0, 0); CP_COMMIT();

    for (int c = 0; c < NCH; c++) {
        int buf = c & 1;
        if (c + 1 < NCH) { load_chunk(c + 1, buf ^ 1); CP_COMMIT(); CP_WAIT(1); }
        else             { CP_WAIT(0); }
        __syncthreads();

        const uint32_t* wA  = (const uint32_t*)sA[buf];
        const uint32_t* wBh = (const uint32_t*)sBh[buf];
        const uint32_t* wBl = (const uint32_t*)sBl[buf];
        #pragma unroll
        for (int ks = 0; ks < 2; ks++) {
            int kw = ks * 8;
            uint32_t a[2][4];
            #pragma unroll
            for (int mi = 0; mi < 2; mi++) {
                int r0 = wm*32 + mi*16 + gq;
                a[mi][0] = wA[r0*20 + kw + q];
                a[mi][1] = wA[(r0+8)*20 + kw + q];
                a[mi][2] = wA[r0*20 + kw + 4 + q];
                a[mi][3] = wA[(r0+8)*20 + kw + 4 + q];
            }
            #pragma unroll
            for (int nt = 0; nt < 4; nt++) {
                int n = wn*32 + nt*8 + gq;
                uint32_t bh0 = wBh[n*20 + kw + q];
                uint32_t bh1 = wBh[n*20 + kw + 4 + q];
                MMA_OP(acc[0][nt], a[0][0],a[0][1],a[0][2],a[0][3], bh0, bh1);
                MMA_OP(acc[1][nt], a[1][0],a[1][1],a[1][2],a[1][3], bh0, bh1);
                uint32_t bl0 = wBl[n*20 + kw + q];
                uint32_t bl1 = wBl[n*20 + kw + 4 + q];
                MMA_OP(acc[0][nt], a[0][0],a[0][1],a[0][2],a[0][3], bl0, bl1);
                MMA_OP(acc[1][nt], a[1][0],a[1][1],a[1][2],a[1][3], bl0, bl1);
            }
        }
        __syncthreads();
    }

    #pragma unroll
    for (int mi = 0; mi < 2; mi++) {
        int r0 = m0 + wm*32 + mi*16 + gq;
        #pragma unroll
        for (int nt = 0; nt < 4; nt++) {
            int n = n0 + wn*32 + nt*8 + q*2;
            float b0 = 0.f, b1 = 0.f;
            if (LAYER != 2) { b0 = bias[n]; b1 = bias[n+1]; }
            float2 v0; v0.x = acc[mi][nt][0] + b0; v0.y = acc[mi][nt][1] + b1;
            float2 v1; v1.x = acc[mi][nt][2] + b0; v1.y = acc[mi][nt][3] + b1;
            *(float2*)(C + (size_t)r0*NTOT + n) = v0;
            *(float2*)(C + (size_t)(r0+8)*NTOT + n) = v1;
        }
    }
}

// ================= BN gather (layout [rows][64]) + finalize =================
template<int SEL>
__global__ void __launch_bounds__(256) k_bngather()
{
    const float* h = (SEL == 0) ? g_h2 : g_h3;
    constexpr int rows = (SEL == 0) ? 82944 : 50176;
    float* sum = (SEL == 0) ? g_bnacc       : g_bnacc + 128;
    float* sq  = (SEL == 0) ? g_bnacc + 64  : g_bnacc + 192;
    int gw = blockIdx.x*8 + (threadIdx.x >> 5);
    int lid = threadIdx.x & 31;
    int W = gridDim.x * 8;
    float s0 = 0.f, q0 = 0.f, s1 = 0.f, q1 = 0.f;
    for (int r = gw; r < rows; r += W) {
        float a = h[(size_t)r*64 + lid];
        float b = h[(size_t)r*64 + 32 + lid];
        s0 += a; q0 += a*a; s1 += b; q1 += b*b;
    }
    atomicAdd(&sum[lid], s0);      atomicAdd(&sq[lid], q0);
    atomicAdd(&sum[32+lid], s1);   atomicAdd(&sq[32+lid], q1);
}

template<int SEL>
__global__ void k_bnfin()
{
    const float* sum = (SEL == 0) ? g_bnacc      : g_bnacc + 128;
    const float* sq  = (SEL == 0) ? g_bnacc + 64 : g_bnacc + 192;
    float* mean = (SEL == 0) ? g_mean2 : g_mean3;
    float* rstd = (SEL == 0) ? g_rstd2 : g_rstd3;
    constexpr float invn = (SEL == 0) ? (1.f/82944.f) : (1.f/50176.f);
    int c = threadIdx.x;
    if (c >= 64) return;
    float m = sum[c] * invn;
    float v = sq[c] * invn - m*m;
    mean[c] = m;
    rstd[c] = rsqrtf(v + 1e-5f);
}

// ================= LIF layer 2: planar, fully coalesced (s2b layout == h2 layout) ==========
__global__ void k_lif2(const float* __restrict__ gamma, const float* __restrict__ beta)
{
    int idx = blockIdx.x*blockDim.x + threadIdx.x;
    if (idx >= 128*81*64) return;
    int c = idx & 63;
    float m = g_mean2[c];
    float sc = g_rstd2[c]*gamma[c];
    float be = beta[c];
    float v = 0.f;
    #pragma unroll
    for (int t = 0; t < 8; t++) {
        float a = (g_h2[(size_t)t*663552 + idx] - m)*sc + be;
        v = v + (a - v)*0.5f;
        float s = (v >= 1.0f) ? 1.0f : 0.0f;
        g_s2b[(size_t)t*663552 + idx] = __float2bfloat16(s);
        v = v * (1.0f - s);
    }
}

// ================= im2col for conv3 (s2b is [tb][pos][c]) =================
__global__ void __launch_bounds__(256) k_im2col3()
{
    __shared__ __align__(16) __nv_bfloat16 s_t[5184];   // [pos(81)][c(64)]
    int tb = blockIdx.x;
    const uint4* src = (const uint4*)(g_s2b + (size_t)tb*5184);
    for (int i = threadIdx.x; i < 648; i += 256) ((uint4*)s_t)[i] = src[i];
    __syncthreads();
    for (int task = threadIdx.x; task < 3136; task += 256) {
        int pos = task >> 6, c = task & 63;
        int oy = pos / 7, ox = pos - oy*7;
        const __nv_bfloat16* w = s_t + (oy*9 + ox)*64 + c;
        __nv_bfloat16* dst = g_A3 + (size_t)(tb*49 + pos)*576 + c;
        #pragma unroll
        for (int ky = 0; ky < 3; ky++)
            #pragma unroll
            for (int kx = 0; kx < 3; kx++)
                dst[(ky*3+kx)*64] = w[(ky*9 + kx)*64];
    }
}

// ================= LIF layer 3: smem-staged transpose, coalesced in+out ==========
// grid (128 b, 2 c-halves); h3[(tb*49+pos)*64+c] -> A4[tb*3136 + c*49+pos]
__global__ void __launch_bounds__(256) k_lif3(const float* __restrict__ gamma,
                                              const float* __restrict__ beta)
{
    __shared__ __align__(16) __nv_bfloat16 sp[8][32*49];   // 25088 B
    int b = blockIdx.x, ch = blockIdx.y;
    for (int i = threadIdx.x; i < 1568; i += 256) {
        int pos = i >> 5, cl = i & 31;
        int c = ch*32 + cl;
        float m = g_mean3[c];
        float sc = g_rstd3[c]*gamma[c];
        float be = beta[c];
        float v = 0.f;
        #pragma unroll
        for (int t = 0; t < 8; t++) {
            float a = (g_h3[((size_t)(t*128 + b)*49 + pos)*64 + c] - m)*sc + be;
            v = v + (a - v)*0.5f;
            float s = (v >= 1.0f) ? 1.0f : 0.0f;
            sp[t][cl*49 + pos] = __float2bfloat16(s);
            v = v * (1.0f - s);
        }
    }
    __syncthreads();
    for (int i = threadIdx.x; i < 1568; i += 256) {   // 8 planes x 196 uint4
        int t = i / 196, j = i - t*196;
        *(uint4*)(g_A4 + (size_t)(t*128 + b)*3136 + ch*1568 + j*8) = ((const uint4*)sp[t])[j];
    }
}

// ================= LIF layer 4 (sums 2 K-split partials + bias) + spike counts ==========
__global__ void k_lif4(const float* __restrict__ fb)
{
    int idx = blockIdx.x*blockDim.x + threadIdx.x;
    if (idx >= 128*512) return;
    int b = idx >> 9, o = idx & 511;
    float bb = fb[o];
    float v = 0.f, cnt = 0.f;
    #pragma unroll
    for (int t = 0; t < 8; t++) {
        int j = (t*128 + b)*512 + o;
        float a = g_h4[j] + g_h4[524288 + j] + bb;
        v = v + (a - v)*0.5f;
        float s = (v >= 1.0f) ? 1.0f : 0.0f;
        cnt += s;
        v = v * (1.0f - s);
    }
    g_cnt[idx] = cnt;
}

// ================= final fco + mean over T =================
__global__ void __launch_bounds__(128) k_out(const float* __restrict__ fco_w,
                                             const float* __restrict__ fco_b,
                                             float* __restrict__ out)
{
    int b = blockIdx.x, tid = threadIdx.x;
    float p0 = 0.f, p1 = 0.f;
    for (int o = tid; o < 512; o += 128) {
        float c = g_cnt[b*512 + o];
        p0 += c * fco_w[o];
        p1 += c * fco_w[512 + o];
    }
    __shared__ float s0[128], s1[128];
    s0[tid] = p0; s1[tid] = p1;
    __syncthreads();
    for (int k = 64; k > 0; k >>= 1) {
        if (tid < k) { s0[tid] += s0[tid+k]; s1[tid] += s1[tid+k]; }
        __syncthreads();
    }
    if (tid == 0) {
        out[b*2 + 0] = fco_b[0] + s0[0] * 0.125f;
        out[b*2 + 1] = fco_b[1] + s1[0] * 0.125f;
    }
}

// ================= launch =================
extern "C" void kernel_launch(void* const* d_in, const int* in_sizes, int n_in,
                              void* d_out, int out_size)
{
    const float* x   = (const float*)d_in[0];
    const float* c1w = (const float*)d_in[1];
    const float* c1b = (const float*)d_in[2];
    const float* g1  = (const float*)d_in[3];
    const float* b1  = (const float*)d_in[4];
    const float* c2w = (const float*)d_in[5];
    const float* c2b = (const float*)d_in[6];
    const float* g2  = (const float*)d_in[7];
    const float* b2  = (const float*)d_in[8];
    const float* c3w = (const float*)d_in[9];
    const float* c3b = (const float*)d_in[10];
    const float* g3  = (const float*)d_in[11];
    const float* b3  = (const float*)d_in[12];
    const float* fw  = (const float*)d_in[13];
    const float* fb  = (const float*)d_in[14];
    const float* ow  = (const float*)d_in[15];
    const float* ob  = (const float*)d_in[16];
    float* out = (float*)d_out;

    cudaFuncSetAttribute(k_conv1, cudaFuncAttributeMaxDynamicSharedMemorySize, SMEM1);

    k_zero<<<1, 256>>>();
    k_wsplit<0><<<(64*512 + 255)/256, 256>>>(c2w);
    k_wsplit<1><<<(64*576 + 255)/256, 256>>>(c3w);
    k_wsplit<2><<<(512*3136 + 255)/256, 256>>>(fw);

    k_conv1<<<128, 256, SMEM1>>>(x, c1w, c1b);
    k_bnstats1<<<32, 256>>>();
    k_lif1<<<(1638400 + 255)/256, 256>>>(g1, b1);

    k_im2col2<<<1024, 256>>>();
    k_gemm<0><<<dim3(648, 1), 256>>>(c2b);
    k_bngather<0><<<256, 256>>>();
    k_bnfin<0><<<1, 64>>>();
    k_lif2<<<(663552 + 255)/256, 256>>>(g2, b2);

    k_im2col3<<<1024, 256>>>();
    k_gemm<1><<<dim3(392, 1), 256>>>(c3b);
    k_bngather<1><<<128, 256>>>();
    k_bnfin<1><<<1, 64>>>();
    k_lif3<<<dim3(128, 2), 256>>>(g3, b3);

    k_gemm<2><<<dim3(8, 8, 2), 256>>>(fb);
    k_lif4<<<256, 256>>>(fb);
    k_out<<<128, 128>>>(ow, ob, out);
}

// round 9
// speedup vs baseline: 4.3038x; 1.0243x over previous
#include <cuda_runtime.h>
#include <cuda_bf16.h>
#include <cstdint>

// ================= scratch (device globals; no allocation allowed) =================
__device__ __align__(16) float g_h1[128*400*32];                  // conv1 out [b][pix][c]
__device__ __align__(16) __nv_bfloat16 g_s1b[8*128*400*32];       // spikes L1 [t][b][pix][c32]
__device__ __align__(16) float g_h2[82944*64];                    // conv2 out [tb*81+pos][c]
__device__ __align__(16) __nv_bfloat16 g_s2b[8*128*81*64];        // spikes L2 [tb][pos][c64]
__device__ __align__(16) float g_h3[50176*64];                    // conv3 out [tb*49+pos][c]
__device__ __align__(16) __nv_bfloat16 g_s3b[1024*3136];          // spikes L3 [tb][pos*64+c]
__device__ __align__(16) float g_h4[2*1024*512];                  // fc1 out (2 K-split partials)
__device__ __align__(16) float g_cnt[128*512];
__device__ float g_mean1[32], g_rstd1[32];
__device__ float g_mean2[64], g_rstd2[64];
__device__ float g_mean3[64], g_rstd3[64];
__device__ float g_bnacc[256];    // [sum2(64)|sq2(64)|sum3(64)|sq3(64)]
__device__ float g_bn1acc[64];    // [sum1(32)|sq1(32)]
__device__ __align__(16) __nv_bfloat16 g_w2hi[64*512],  g_w2lo[64*512];
__device__ __align__(16) __nv_bfloat16 g_w3hi[64*576],  g_w3lo[64*576];
__device__ __align__(16) __nv_bfloat16 g_wfhi[512*3136], g_wflo[512*3136];

// ================= helpers =================
__device__ __forceinline__ uint32_t smem_u32(const void* p) {
    return (uint32_t)__cvta_generic_to_shared(p);
}
#define CP16(dst_u32, src_ptr) \
    asm volatile("cp.async.cg.shared.global [%0], [%1], 16;" :: "r"(dst_u32), "l"(src_ptr))
#define CP_COMMIT() asm volatile("cp.async.commit_group;" ::: "memory")
#define CP_WAIT(n)  asm volatile("cp.async.wait_group %0;" :: "n"(n) : "memory")

// ================= conv1 (fp32): [128,4,84,84] -> h1[b][pix(400)][c(32)] =================
#define SMEM1 ((28224 + 256*33)*4)
__global__ void __launch_bounds__(256) k_conv1(const float* __restrict__ x,
                                               const float* __restrict__ w,
                                               const float* __restrict__ bias)
{
    extern __shared__ float sm[];
    float* s_in = sm;
    float* s_w  = sm + 28224;
    const int n = blockIdx.x, tid = threadIdx.x;

    const float4* gx = (const float4*)(x + n*28224);
    for (int i = tid; i < 7056; i += 256) ((float4*)s_in)[i] = gx[i];
    for (int i = tid; i < 8192; i += 256) {
        int oc = i >> 8, tap = i & 255;
        s_w[tap*33 + oc] = w[i];
    }
    __syncthreads();

    for (int task = tid; task < 400; task += 256) {
        int ocg = task & 3, posg = task >> 2;
        int oc0 = ocg * 8, p0 = posg * 4;
        float acc[8][4];
        #pragma unroll
        for (int i = 0; i < 8; i++)
            #pragma unroll
            for (int j = 0; j < 4; j++) acc[i][j] = 0.f;
        int base[4];
        #pragma unroll
        for (int j = 0; j < 4; j++) {
            int p = p0 + j, oy = p / 20, ox = p - oy*20;
            base[j] = oy*4*84 + ox*4;
        }
        for (int ic = 0; ic < 4; ic++) {
            #pragma unroll
            for (int ky = 0; ky < 8; ky++) {
                int ib = ic*7056 + ky*84;
                const float* wrow = s_w + (ic*64 + ky*8)*33 + oc0;
                #pragma unroll
                for (int kx = 0; kx < 8; kx++) {
                    float in0 = s_in[base[0]+ib+kx];
                    float in1 = s_in[base[1]+ib+kx];
                    float in2 = s_in[base[2]+ib+kx];
                    float in3 = s_in[base[3]+ib+kx];
                    const float* wp = wrow + kx*33;
                    #pragma unroll
                    for (int i = 0; i < 8; i++) {
                        float wf = wp[i];
                        acc[i][0] += wf*in0; acc[i][1] += wf*in1;
                        acc[i][2] += wf*in2; acc[i][3] += wf*in3;
                    }
                }
            }
        }
        #pragma unroll
        for (int j = 0; j < 4; j++) {
            #pragma unroll
            for (int i = 0; i < 8; i++)
                g_h1[(n*400 + p0+j)*32 + oc0+i] = acc[i][j] + bias[oc0+i];
        }
    }
}

// ================= BN stats layer 1: gather over [b*pix rows][c32] =================
__global__ void __launch_bounds__(256) k_bnstats1()
{
    int gw = blockIdx.x*8 + (threadIdx.x >> 5);
    int lane = threadIdx.x & 31;
    int W = gridDim.x * 8;
    float s = 0.f, q = 0.f;
    for (int r = gw; r < 51200; r += W) {
        float v = g_h1[r*32 + lane];
        s += v; q += v*v;
    }
    atomicAdd(&g_bn1acc[lane], s);
    atomicAdd(&g_bn1acc[32 + lane], q);
}

__global__ void k_bnfin1()
{
    int c = threadIdx.x;
    if (c >= 32) return;
    float m = g_bn1acc[c] / 51200.f;
    float v = g_bn1acc[32 + c] / 51200.f - m*m;
    g_mean1[c] = m;
    g_rstd1[c] = rsqrtf(v + 1e-5f);
}

// ================= LIF layer 1 -> bf16 spikes (planar, coalesced) =================
__global__ void k_lif1(const float* __restrict__ gamma, const float* __restrict__ beta)
{
    int idx = blockIdx.x*blockDim.x + threadIdx.x;
    if (idx >= 128*400*32) return;
    int c = idx & 31;
    float a = (g_h1[idx] - g_mean1[c]) * g_rstd1[c] * gamma[c] + beta[c];
    float v = 0.f;
    #pragma unroll
    for (int t = 0; t < 8; t++) {
        v = v + (a - v)*0.5f;
        float s = (v >= 1.0f) ? 1.0f : 0.0f;
        g_s1b[t*1638400 + idx] = __float2bfloat16(s);
        v = v * (1.0f - s);
    }
}

// ================= weight split -> bf16 hi/lo, tap order matched to A layouts ==========
template<int SEL>
__global__ void k_wsplit(const float* __restrict__ src)
{
    constexpr int OC = (SEL == 0) ? 64 : (SEL == 1) ? 64 : 512;
    constexpr int K  = (SEL == 0) ? 512 : (SEL == 1) ? 576 : 3136;
    __nv_bfloat16* hi = (SEL == 0) ? g_w2hi : (SEL == 1) ? g_w3hi : g_wfhi;
    __nv_bfloat16* lo = (SEL == 0) ? g_w2lo : (SEL == 1) ? g_w3lo : g_wflo;
    int idx = blockIdx.x*256 + threadIdx.x;
    if (idx >= OC*K) return;
    int oc = idx / K, rem = idx - oc*K;
    int tap;
    if (SEL == 0) {        // src i = ic*16 + kk  ->  tap = kk*32 + ic
        int ic = rem >> 4, kk = rem & 15;
        tap = kk*32 + ic;
    } else if (SEL == 1) { // src i = ic*9 + kk   ->  tap = kk*64 + ic
        int ic = rem / 9, kk = rem - ic*9;
        tap = kk*64 + ic;
    } else {               // src i = c*49 + pos  ->  tap = pos*64 + c
        int c = rem / 49, pos = rem - c*49;
        tap = pos*64 + c;
    }
    float w = src[idx];
    __nv_bfloat16 h = __float2bfloat16(w);
    float hf = __bfloat162float(h);
    hi[oc*K + tap] = h;
    lo[oc*K + tap] = __float2bfloat16(w - hf);
}

__global__ void k_zero()
{
    if (threadIdx.x < 256) g_bnacc[threadIdx.x] = 0.f;
    if (threadIdx.x < 64)  g_bn1acc[threadIdx.x] = 0.f;
}

// ================= bf16 mma.sync GEMM, cp.async double-buffered, implicit im2col A ==========
// block tile 128x64, 8 warps (4m x 2n), warp tile 32x32, K-chunk 32.
#define MMA_OP(d, a0,a1,a2,a3, b0,b1) \
    asm volatile("mma.sync.aligned.m16n8k16.row.col.f32.bf16.bf16.f32 " \
        "{%0,%1,%2,%3}, {%4,%5,%6,%7}, {%8,%9}, {%0,%1,%2,%3};" \
        : "+f"((d)[0]), "+f"((d)[1]), "+f"((d)[2]), "+f"((d)[3]) \
        : "r"(a0), "r"(a1), "r"(a2), "r"(a3), "r"(b0), "r"(b1))

template<int LAYER>
__global__ void __launch_bounds__(256) k_gemm(const float* __restrict__ bias)
{
    constexpr int K    = (LAYER == 0) ? 512 : (LAYER == 1) ? 576 : 3136;
    constexpr int NTOT = (LAYER == 2) ? 512 : 64;
    constexpr int NCH  = (LAYER == 0) ? 16 : (LAYER == 1) ? 18 : 49;
    const __nv_bfloat16* Asrc = (LAYER == 0) ? g_s1b : (LAYER == 1) ? g_s2b : g_s3b;
    const __nv_bfloat16* Bhi = (LAYER == 0) ? g_w2hi: (LAYER == 1) ? g_w3hi: g_wfhi;
    const __nv_bfloat16* Blo = (LAYER == 0) ? g_w2lo: (LAYER == 1) ? g_w3lo: g_wflo;
    float* C                 = (LAYER == 0) ? g_h2  : (LAYER == 1) ? g_h3
                                            : g_h4 + (size_t)blockIdx.z*524288;
    const int cbase = (LAYER == 2) ? blockIdx.z*49 : 0;

    __shared__ __align__(16) __nv_bfloat16 sA[2][128*40];
    __shared__ __align__(16) __nv_bfloat16 sBh[2][64*40];
    __shared__ __align__(16) __nv_bfloat16 sBl[2][64*40];

    const int tid = threadIdx.x;
    const int wid = tid >> 5, lane = tid & 31;
    const int gq = lane >> 2, q = lane & 3;
    const int wm = wid & 3, wn = wid >> 2;
    const int m0 = blockIdx.x * 128, n0 = blockIdx.y * 64;

    uint32_t uA[2]  = { smem_u32(sA[0]),  smem_u32(sA[1]) };
    uint32_t uBh[2] = { smem_u32(sBh[0]), smem_u32(sBh[1]) };
    uint32_t uBl[2] = { smem_u32(sBl[0]), smem_u32(sBl[1]) };

    // per-thread A-row bases (2 rows per thread: r and r+64)
    const int gg = tid & 3;
    size_t abase[2];
    uint32_t adst[2];
    #pragma unroll
    for (int it = 0; it < 2; it++) {
        int r = (tid >> 2) + it*64;
        int rg = m0 + r;
        if (LAYER == 0) {
            int tb = rg / 81, pos = rg - tb*81;
            int oy = pos / 9, ox = pos - oy*9;
            abase[it] = (size_t)tb*12800 + (size_t)(oy*40 + ox*2)*32 + gg*8;
        } else if (LAYER == 1) {
            int tb = rg / 49, pos = rg - tb*49;
            int oy = pos / 7, ox = pos - oy*7;
            abase[it] = (size_t)tb*5184 + (size_t)(oy*9 + ox)*64 + gg*8;
        } else {
            abase[it] = (size_t)rg*3136 + gg*8;
        }
        adst[it] = (uint32_t)(r*40 + gg*8)*2;
    }

    auto load_chunk = [&](int cc, int buf) {
        int aoff;
        if (LAYER == 0) {
            int ky = cc >> 2, kx = cc & 3;
            aoff = (ky*20 + kx)*32;
        } else if (LAYER == 1) {
            int kk = cc >> 1, half = cc & 1;
            int ky = kk / 3, kx = kk - ky*3;
            aoff = (ky*9 + kx)*64 + half*32;
        } else {
            aoff = (cbase + cc) << 5;
        }
        #pragma unroll
        for (int it = 0; it < 2; it++)
            CP16(uA[buf] + adst[it], Asrc + abase[it] + aoff);
        int k0 = (cbase + cc) << 5;
        int r = tid >> 2;
        CP16(uBh[buf] + (uint32_t)(r*40 + gg*8)*2, Bhi + (size_t)(n0 + r)*K + k0 + gg*8);
        CP16(uBl[buf] + (uint32_t)(r*40 + gg*8)*2, Blo + (size_t)(n0 + r)*K + k0 + gg*8);
    };

    float acc[2][4][4];
    #pragma unroll
    for (int mi = 0; mi < 2; mi++)
        #pragma unroll
        for (int nt = 0; nt < 4; nt++)
            #pragma unroll
            for (int j = 0; j < 4; j++) acc[mi][nt][j] = 0.f;

    load_chunk(0, 0); CP_COMMIT();

    for (int c = 0; c < NCH; c++) {
        int buf = c & 1;
        if (c + 1 < NCH) { load_chunk(c + 1, buf ^ 1); CP_COMMIT(); CP_WAIT(1); }
        else             { CP_WAIT(0); }
        __syncthreads();

        const uint32_t* wA  = (const uint32_t*)sA[buf];
        const uint32_t* wBh = (const uint32_t*)sBh[buf];
        const uint32_t* wBl = (const uint32_t*)sBl[buf];
        #pragma unroll
        for (int ks = 0; ks < 2; ks++) {
            int kw = ks * 8;
            uint32_t a[2][4];
            #pragma unroll
            for (int mi = 0; mi < 2; mi++) {
                int r0 = wm*32 + mi*16 + gq;
                a[mi][0] = wA[r0*20 + kw + q];
                a[mi][1] = wA[(r0+8)*20 + kw + q];
                a[mi][2] = wA[r0*20 + kw + 4 + q];
                a[mi][3] = wA[(r0+8)*20 + kw + 4 + q];
            }
            #pragma unroll
            for (int nt = 0; nt < 4; nt++) {
                int n = wn*32 + nt*8 + gq;
                uint32_t bh0 = wBh[n*20 + kw + q];
                uint32_t bh1 = wBh[n*20 + kw + 4 + q];
                MMA_OP(acc[0][nt], a[0][0],a[0][1],a[0][2],a[0][3], bh0, bh1);
                MMA_OP(acc[1][nt], a[1][0],a[1][1],a[1][2],a[1][3], bh0, bh1);
                uint32_t bl0 = wBl[n*20 + kw + q];
                uint32_t bl1 = wBl[n*20 + kw + 4 + q];
                MMA_OP(acc[0][nt], a[0][0],a[0][1],a[0][2],a[0][3], bl0, bl1);
                MMA_OP(acc[1][nt], a[1][0],a[1][1],a[1][2],a[1][3], bl0, bl1);
            }
        }
        __syncthreads();
    }

    #pragma unroll
    for (int mi = 0; mi < 2; mi++) {
        int r0 = m0 + wm*32 + mi*16 + gq;
        #pragma unroll
        for (int nt = 0; nt < 4; nt++) {
            int n = n0 + wn*32 + nt*8 + q*2;
            float b0 = 0.f, b1 = 0.f;
            if (LAYER != 2) { b0 = bias[n]; b1 = bias[n+1]; }
            float2 v0; v0.x = acc[mi][nt][0] + b0; v0.y = acc[mi][nt][1] + b1;
            float2 v1; v1.x = acc[mi][nt][2] + b0; v1.y = acc[mi][nt][3] + b1;
            *(float2*)(C + (size_t)r0*NTOT + n) = v0;
            *(float2*)(C + (size_t)(r0+8)*NTOT + n) = v1;
        }
    }
}

// ================= BN gather (layout [rows][64]) + finalize =================
template<int SEL>
__global__ void __launch_bounds__(256) k_bngather()
{
    const float* h = (SEL == 0) ? g_h2 : g_h3;
    constexpr int rows = (SEL == 0) ? 82944 : 50176;
    float* sum = (SEL == 0) ? g_bnacc       : g_bnacc + 128;
    float* sq  = (SEL == 0) ? g_bnacc + 64  : g_bnacc + 192;
    int gw = blockIdx.x*8 + (threadIdx.x >> 5);
    int lid = threadIdx.x & 31;
    int W = gridDim.x * 8;
    float s0 = 0.f, q0 = 0.f, s1 = 0.f, q1 = 0.f;
    for (int r = gw; r < rows; r += W) {
        float a = h[(size_t)r*64 + lid];
        float b = h[(size_t)r*64 + 32 + lid];
        s0 += a; q0 += a*a; s1 += b; q1 += b*b;
    }
    atomicAdd(&sum[lid], s0);      atomicAdd(&sq[lid], q0);
    atomicAdd(&sum[32+lid], s1);   atomicAdd(&sq[32+lid], q1);
}

template<int SEL>
__global__ void k_bnfin()
{
    const float* sum = (SEL == 0) ? g_bnacc      : g_bnacc + 128;
    const float* sq  = (SEL == 0) ? g_bnacc + 64 : g_bnacc + 192;
    float* mean = (SEL == 0) ? g_mean2 : g_mean3;
    float* rstd = (SEL == 0) ? g_rstd2 : g_rstd3;
    constexpr float invn = (SEL == 0) ? (1.f/82944.f) : (1.f/50176.f);
    int c = threadIdx.x;
    if (c >= 64) return;
    float m = sum[c] * invn;
    float v = sq[c] * invn - m*m;
    mean[c] = m;
    rstd[c] = rsqrtf(v + 1e-5f);
}

// ================= LIF layer 2: planar, fully coalesced =================
__global__ void k_lif2(const float* __restrict__ gamma, const float* __restrict__ beta)
{
    int idx = blockIdx.x*blockDim.x + threadIdx.x;
    if (idx >= 128*81*64) return;
    int c = idx & 63;
    float m = g_mean2[c];
    float sc = g_rstd2[c]*gamma[c];
    float be = beta[c];
    float v = 0.f;
    #pragma unroll
    for (int t = 0; t < 8; t++) {
        float a = (g_h2[(size_t)t*663552 + idx] - m)*sc + be;
        v = v + (a - v)*0.5f;
        float s = (v >= 1.0f) ? 1.0f : 0.0f;
        g_s2b[(size_t)t*663552 + idx] = __float2bfloat16(s);
        v = v * (1.0f - s);
    }
}

// ================= LIF layer 3: planar (weights permuted to match) =================
__global__ void k_lif3(const float* __restrict__ gamma, const float* __restrict__ beta)
{
    int idx = blockIdx.x*blockDim.x + threadIdx.x;
    if (idx >= 128*49*64) return;
    int c = idx & 63;
    float m = g_mean3[c];
    float sc = g_rstd3[c]*gamma[c];
    float be = beta[c];
    float v = 0.f;
    #pragma unroll
    for (int t = 0; t < 8; t++) {
        float a = (g_h3[(size_t)t*401408 + idx] - m)*sc + be;
        v = v + (a - v)*0.5f;
        float s = (v >= 1.0f) ? 1.0f : 0.0f;
        g_s3b[(size_t)t*401408 + idx] = __float2bfloat16(s);
        v = v * (1.0f - s);
    }
}

// ================= LIF layer 4 (sums 2 K-split partials + bias) + spike counts ==========
__global__ void k_lif4(const float* __restrict__ fb)
{
    int idx = blockIdx.x*blockDim.x + threadIdx.x;
    if (idx >= 128*512) return;
    int b = idx >> 9, o = idx & 511;
    float bb = fb[o];
    float v = 0.f, cnt = 0.f;
    #pragma unroll
    for (int t = 0; t < 8; t++) {
        int j = (t*128 + b)*512 + o;
        float a = g_h4[j] + g_h4[524288 + j] + bb;
        v = v + (a - v)*0.5f;
        float s = (v >= 1.0f) ? 1.0f : 0.0f;
        cnt += s;
        v = v * (1.0f - s);
    }
    g_cnt[idx] = cnt;
}

// ================= final fco + mean over T =================
__global__ void __launch_bounds__(128) k_out(const float* __restrict__ fco_w,
                                             const float* __restrict__ fco_b,
                                             float* __restrict__ out)
{
    int b = blockIdx.x, tid = threadIdx.x;
    float p0 = 0.f, p1 = 0.f;
    for (int o = tid; o < 512; o += 128) {
        float c = g_cnt[b*512 + o];
        p0 += c * fco_w[o];
        p1 += c * fco_w[512 + o];
    }
    __shared__ float s0[128], s1[128];
    s0[tid] = p0; s1[tid] = p1;
    __syncthreads();
    for (int k = 64; k > 0; k >>= 1) {
        if (tid < k) { s0[tid] += s0[tid+k]; s1[tid] += s1[tid+k]; }
        __syncthreads();
    }
    if (tid == 0) {
        out[b*2 + 0] = fco_b[0] + s0[0] * 0.125f;
        out[b*2 + 1] = fco_b[1] + s1[0] * 0.125f;
    }
}

// ================= launch =================
extern "C" void kernel_launch(void* const* d_in, const int* in_sizes, int n_in,
                              void* d_out, int out_size)
{
    const float* x   = (const float*)d_in[0];
    const float* c1w = (const float*)d_in[1];
    const float* c1b = (const float*)d_in[2];
    const float* g1  = (const float*)d_in[3];
    const float* b1  = (const float*)d_in[4];
    const float* c2w = (const float*)d_in[5];
    const float* c2b = (const float*)d_in[6];
    const float* g2  = (const float*)d_in[7];
    const float* b2  = (const float*)d_in[8];
    const float* c3w = (const float*)d_in[9];
    const float* c3b = (const float*)d_in[10];
    const float* g3  = (const float*)d_in[11];
    const float* b3  = (const float*)d_in[12];
    const float* fw  = (const float*)d_in[13];
    const float* fb  = (const float*)d_in[14];
    const float* ow  = (const float*)d_in[15];
    const float* ob  = (const float*)d_in[16];
    float* out = (float*)d_out;

    cudaFuncSetAttribute(k_conv1, cudaFuncAttributeMaxDynamicSharedMemorySize, SMEM1);

    k_zero<<<1, 256>>>();
    k_wsplit<0><<<(64*512 + 255)/256, 256>>>(c2w);
    k_wsplit<1><<<(64*576 + 255)/256, 256>>>(c3w);
    k_wsplit<2><<<(512*3136 + 255)/256, 256>>>(fw);

    k_conv1<<<128, 256, SMEM1>>>(x, c1w, c1b);
    k_bnstats1<<<128, 256>>>();
    k_bnfin1<<<1, 32>>>();
    k_lif1<<<(1638400 + 255)/256, 256>>>(g1, b1);

    k_gemm<0><<<dim3(648, 1), 256>>>(c2b);
    k_bngather<0><<<256, 256>>>();
    k_bnfin<0><<<1, 64>>>();
    k_lif2<<<(663552 + 255)/256, 256>>>(g2, b2);

    k_gemm<1><<<dim3(392, 1), 256>>>(c3b);
    k_bngather<1><<<128, 256>>>();
    k_bnfin<1><<<1, 64>>>();
    k_lif3<<<(401408 + 255)/256, 256>>>(g3, b3);

    k_gemm<2><<<dim3(8, 8, 2), 256>>>(fb);
    k_lif4<<<256, 256>>>(fb);
    k_out<<<128, 128>>>(ow, ob, out);
}

// round 10
// speedup vs baseline: 4.6633x; 1.0835x over previous
#include <cuda_runtime.h>
#include <cuda_bf16.h>
#include <cstdint>

// ================= scratch (device globals; no allocation allowed) =================
__device__ __align__(16) float g_h1[128*400*32];                  // conv1 out [b][pix][c]
__device__ __align__(16) __nv_bfloat16 g_s1b[8*128*400*32];       // spikes L1 [t][b][pix][c32]
__device__ __align__(16) float g_h2[82944*64];                    // conv2 out [tb*81+pos][c]
__device__ __align__(16) __nv_bfloat16 g_s2b[8*128*81*64];        // spikes L2 [tb][pos][c64]
__device__ __align__(16) float g_h3[50176*64];                    // conv3 out [tb*49+pos][c]
__device__ __align__(16) __nv_bfloat16 g_s3b[1024*3136];          // spikes L3 [tb][pos*64+c]
__device__ __align__(16) float g_h4[2*1024*512];                  // fc1 out (2 K-split partials)
__device__ float g_mean1[32], g_rstd1[32];
__device__ float g_bnacc[256];    // [sum2(64)|sq2(64)|sum3(64)|sq3(64)]
__device__ float g_bn1acc[64];    // [sum1(32)|sq1(32)]
__device__ __align__(16) __nv_bfloat16 g_w2hi[64*512],  g_w2lo[64*512];
__device__ __align__(16) __nv_bfloat16 g_w3hi[64*576],  g_w3lo[64*576];
__device__ __align__(16) __nv_bfloat16 g_wfhi[512*3136], g_wflo[512*3136];

// ================= helpers =================
__device__ __forceinline__ uint32_t smem_u32(const void* p) {
    return (uint32_t)__cvta_generic_to_shared(p);
}
#define CP16(dst_u32, src_ptr) \
    asm volatile("cp.async.cg.shared.global [%0], [%1], 16;" :: "r"(dst_u32), "l"(src_ptr))
#define CP_COMMIT() asm volatile("cp.async.commit_group;" ::: "memory")
#define CP_WAIT(n)  asm volatile("cp.async.wait_group %0;" :: "n"(n) : "memory")

// ================= conv1 (fp32): [128,4,84,84] -> h1[b][pix(400)][c(32)] =================
#define SMEM1 ((28224 + 256*33)*4)
__global__ void __launch_bounds__(256) k_conv1(const float* __restrict__ x,
                                               const float* __restrict__ w,
                                               const float* __restrict__ bias)
{
    extern __shared__ float sm[];
    float* s_in = sm;
    float* s_w  = sm + 28224;
    const int n = blockIdx.x, tid = threadIdx.x;

    const float4* gx = (const float4*)(x + n*28224);
    for (int i = tid; i < 7056; i += 256) ((float4*)s_in)[i] = gx[i];
    for (int i = tid; i < 8192; i += 256) {
        int oc = i >> 8, tap = i & 255;
        s_w[tap*33 + oc] = w[i];
    }
    __syncthreads();

    for (int task = tid; task < 400; task += 256) {
        int ocg = task & 3, posg = task >> 2;
        int oc0 = ocg * 8, p0 = posg * 4;
        float acc[8][4];
        #pragma unroll
        for (int i = 0; i < 8; i++)
            #pragma unroll
            for (int j = 0; j < 4; j++) acc[i][j] = 0.f;
        int base[4];
        #pragma unroll
        for (int j = 0; j < 4; j++) {
            int p = p0 + j, oy = p / 20, ox = p - oy*20;
            base[j] = oy*4*84 + ox*4;
        }
        for (int ic = 0; ic < 4; ic++) {
            #pragma unroll
            for (int ky = 0; ky < 8; ky++) {
                int ib = ic*7056 + ky*84;
                const float* wrow = s_w + (ic*64 + ky*8)*33 + oc0;
                #pragma unroll
                for (int kx = 0; kx < 8; kx++) {
                    float in0 = s_in[base[0]+ib+kx];
                    float in1 = s_in[base[1]+ib+kx];
                    float in2 = s_in[base[2]+ib+kx];
                    float in3 = s_in[base[3]+ib+kx];
                    const float* wp = wrow + kx*33;
                    #pragma unroll
                    for (int i = 0; i < 8; i++) {
                        float wf = wp[i];
                        acc[i][0] += wf*in0; acc[i][1] += wf*in1;
                        acc[i][2] += wf*in2; acc[i][3] += wf*in3;
                    }
                }
            }
        }
        #pragma unroll
        for (int j = 0; j < 4; j++) {
            #pragma unroll
            for (int i = 0; i < 8; i++)
                g_h1[(n*400 + p0+j)*32 + oc0+i] = acc[i][j] + bias[oc0+i];
        }
    }
}

// ================= BN stats layer 1: gather over [b*pix rows][c32] =================
__global__ void __launch_bounds__(256) k_bnstats1()
{
    int gw = blockIdx.x*8 + (threadIdx.x >> 5);
    int lane = threadIdx.x & 31;
    int W = gridDim.x * 8;
    float s = 0.f, q = 0.f;
    for (int r = gw; r < 51200; r += W) {
        float v = g_h1[r*32 + lane];
        s += v; q += v*v;
    }
    atomicAdd(&g_bn1acc[lane], s);
    atomicAdd(&g_bn1acc[32 + lane], q);
}

// ================= LIF layer 1 (BN finalize inlined) -> bf16 spikes =================
__global__ void k_lif1(const float* __restrict__ gamma, const float* __restrict__ beta)
{
    int idx = blockIdx.x*blockDim.x + threadIdx.x;
    if (idx >= 128*400*32) return;
    int c = idx & 31;
    float m = g_bn1acc[c] * (1.f/51200.f);
    float var = g_bn1acc[32 + c] * (1.f/51200.f) - m*m;
    float a = (g_h1[idx] - m) * rsqrtf(var + 1e-5f) * gamma[c] + beta[c];
    float v = 0.f;
    #pragma unroll
    for (int t = 0; t < 8; t++) {
        v = v + (a - v)*0.5f;
        float s = (v >= 1.0f) ? 1.0f : 0.0f;
        g_s1b[t*1638400 + idx] = __float2bfloat16(s);
        v = v * (1.0f - s);
    }
}

// ================= weight split -> bf16 hi/lo, smem-transposed, coalesced both sides ==========
// block per oc; read row coalesced, permute tap in smem, uint4 coalesced writes.
template<int SEL>
__global__ void __launch_bounds__(256) k_wsplit(const float* __restrict__ src)
{
    constexpr int K   = (SEL == 0) ? 512 : (SEL == 1) ? 576 : 3136;
    constexpr int IC  = (SEL == 0) ? 32 : (SEL == 1) ? 64 : 64;
    constexpr int KHW = (SEL == 0) ? 16 : (SEL == 1) ? 9  : 49;
    __nv_bfloat16* hi = (SEL == 0) ? g_w2hi : (SEL == 1) ? g_w3hi : g_wfhi;
    __nv_bfloat16* lo = (SEL == 0) ? g_w2lo : (SEL == 1) ? g_w3lo : g_wflo;
    __shared__ __align__(16) __nv_bfloat16 shi[K], slo[K];
    int oc = blockIdx.x, tid = threadIdx.x;
    const float* row = src + (size_t)oc*K;
    for (int i = tid; i < K; i += 256) {
        int ic = i / KHW, kk = i - ic*KHW;
        float w = row[i];
        __nv_bfloat16 h = __float2bfloat16(w);
        shi[kk*IC + ic] = h;
        slo[kk*IC + ic] = __float2bfloat16(w - __bfloat162float(h));
    }
    __syncthreads();
    uint4* dh = (uint4*)(hi + (size_t)oc*K);
    uint4* dl = (uint4*)(lo + (size_t)oc*K);
    for (int i = tid; i < K/8; i += 256) {
        dh[i] = ((const uint4*)shi)[i];
        dl[i] = ((const uint4*)slo)[i];
    }
}

__global__ void k_zero()
{
    if (threadIdx.x < 256) g_bnacc[threadIdx.x] = 0.f;
    if (threadIdx.x < 64)  g_bn1acc[threadIdx.x] = 0.f;
}

// ================= bf16 mma.sync GEMM, cp.async double-buffered, implicit im2col A ==========
#define MMA_OP(d, a0,a1,a2,a3, b0,b1) \
    asm volatile("mma.sync.aligned.m16n8k16.row.col.f32.bf16.bf16.f32 " \
        "{%0,%1,%2,%3}, {%4,%5,%6,%7}, {%8,%9}, {%0,%1,%2,%3};" \
        : "+f"((d)[0]), "+f"((d)[1]), "+f"((d)[2]), "+f"((d)[3]) \
        : "r"(a0), "r"(a1), "r"(a2), "r"(a3), "r"(b0), "r"(b1))

template<int LAYER>
__global__ void __launch_bounds__(256) k_gemm(const float* __restrict__ bias)
{
    constexpr int K    = (LAYER == 0) ? 512 : (LAYER == 1) ? 576 : 3136;
    constexpr int NTOT = (LAYER == 2) ? 512 : 64;
    constexpr int NCH  = (LAYER == 0) ? 16 : (LAYER == 1) ? 18 : 49;
    const __nv_bfloat16* Asrc = (LAYER == 0) ? g_s1b : (LAYER == 1) ? g_s2b : g_s3b;
    const __nv_bfloat16* Bhi = (LAYER == 0) ? g_w2hi: (LAYER == 1) ? g_w3hi: g_wfhi;
    const __nv_bfloat16* Blo = (LAYER == 0) ? g_w2lo: (LAYER == 1) ? g_w3lo: g_wflo;
    float* C                 = (LAYER == 0) ? g_h2  : (LAYER == 1) ? g_h3
                                            : g_h4 + (size_t)blockIdx.z*524288;
    const int cbase = (LAYER == 2) ? blockIdx.z*49 : 0;

    __shared__ __align__(16) __nv_bfloat16 sA[2][128*40];
    __shared__ __align__(16) __nv_bfloat16 sBh[2][64*40];
    __shared__ __align__(16) __nv_bfloat16 sBl[2][64*40];

    const int tid = threadIdx.x;
    const int wid = tid >> 5, lane = tid & 31;
    const int gq = lane >> 2, q = lane & 3;
    const int wm = wid & 3, wn = wid >> 2;
    const int m0 = blockIdx.x * 128, n0 = blockIdx.y * 64;

    uint32_t uA[2]  = { smem_u32(sA[0]),  smem_u32(sA[1]) };
    uint32_t uBh[2] = { smem_u32(sBh[0]), smem_u32(sBh[1]) };
    uint32_t uBl[2] = { smem_u32(sBl[0]), smem_u32(sBl[1]) };

    const int gg = tid & 3;
    size_t abase[2];
    uint32_t adst[2];
    #pragma unroll
    for (int it = 0; it < 2; it++) {
        int r = (tid >> 2) + it*64;
        int rg = m0 + r;
        if (LAYER == 0) {
            int tb = rg / 81, pos = rg - tb*81;
            int oy = pos / 9, ox = pos - oy*9;
            abase[it] = (size_t)tb*12800 + (size_t)(oy*40 + ox*2)*32 + gg*8;
        } else if (LAYER == 1) {
            int tb = rg / 49, pos = rg - tb*49;
            int oy = pos / 7, ox = pos - oy*7;
            abase[it] = (size_t)tb*5184 + (size_t)(oy*9 + ox)*64 + gg*8;
        } else {
            abase[it] = (size_t)rg*3136 + gg*8;
        }
        adst[it] = (uint32_t)(r*40 + gg*8)*2;
    }

    auto load_chunk = [&](int cc, int buf) {
        int aoff;
        if (LAYER == 0) {
            int ky = cc >> 2, kx = cc & 3;
            aoff = (ky*20 + kx)*32;
        } else if (LAYER == 1) {
            int kk = cc >> 1, half = cc & 1;
            int ky = kk / 3, kx = kk - ky*3;
            aoff = (ky*9 + kx)*64 + half*32;
        } else {
            aoff = (cbase + cc) << 5;
        }
        #pragma unroll
        for (int it = 0; it < 2; it++)
            CP16(uA[buf] + adst[it], Asrc + abase[it] + aoff);
        int k0 = (cbase + cc) << 5;
        int r = tid >> 2;
        CP16(uBh[buf] + (uint32_t)(r*40 + gg*8)*2, Bhi + (size_t)(n0 + r)*K + k0 + gg*8);
        CP16(uBl[buf] + (uint32_t)(r*40 + gg*8)*2, Blo + (size_t)(n0 + r)*K + k0 + gg*8);
    };

    float acc[2][4][4];
    #pragma unroll
    for (int mi = 0; mi < 2; mi++)
        #pragma unroll
        for (int nt = 0; nt < 4; nt++)
            #pragma unroll
            for (int j = 0; j < 4; j++) acc[mi][nt][j] = 0.f;

    load_chunk(0, 0); CP_COMMIT();

    for (int c = 0; c < NCH; c++) {
        int buf = c & 1;
        if (c + 1 < NCH) { load_chunk(c + 1, buf ^ 1); CP_COMMIT(); CP_WAIT(1); }
        else             { CP_WAIT(0); }
        __syncthreads();

        const uint32_t* wA  = (const uint32_t*)sA[buf];
        const uint32_t* wBh = (const uint32_t*)sBh[buf];
        const uint32_t* wBl = (const uint32_t*)sBl[buf];
        #pragma unroll
        for (int ks = 0; ks < 2; ks++) {
            int kw = ks * 8;
            uint32_t a[2][4];
            #pragma unroll
            for (int mi = 0; mi < 2; mi++) {
                int r0 = wm*32 + mi*16 + gq;
                a[mi][0] = wA[r0*20 + kw + q];
                a[mi][1] = wA[(r0+8)*20 + kw + q];
                a[mi][2] = wA[r0*20 + kw + 4 + q];
                a[mi][3] = wA[(r0+8)*20 + kw + 4 + q];
            }
            #pragma unroll
            for (int nt = 0; nt < 4; nt++) {
                int n = wn*32 + nt*8 + gq;
                uint32_t bh0 = wBh[n*20 + kw + q];
                uint32_t bh1 = wBh[n*20 + kw + 4 + q];
                MMA_OP(acc[0][nt], a[0][0],a[0][1],a[0][2],a[0][3], bh0, bh1);
                MMA_OP(acc[1][nt], a[1][0],a[1][1],a[1][2],a[1][3], bh0, bh1);
                uint32_t bl0 = wBl[n*20 + kw + q];
                uint32_t bl1 = wBl[n*20 + kw + 4 + q];
                MMA_OP(acc[0][nt], a[0][0],a[0][1],a[0][2],a[0][3], bl0, bl1);
                MMA_OP(acc[1][nt], a[1][0],a[1][1],a[1][2],a[1][3], bl0, bl1);
            }
        }
        __syncthreads();
    }

    #pragma unroll
    for (int mi = 0; mi < 2; mi++) {
        int r0 = m0 + wm*32 + mi*16 + gq;
        #pragma unroll
        for (int nt = 0; nt < 4; nt++) {
            int n = n0 + wn*32 + nt*8 + q*2;
            float b0 = 0.f, b1 = 0.f;
            if (LAYER != 2) { b0 = bias[n]; b1 = bias[n+1]; }
            float2 v0; v0.x = acc[mi][nt][0] + b0; v0.y = acc[mi][nt][1] + b1;
            float2 v1; v1.x = acc[mi][nt][2] + b0; v1.y = acc[mi][nt][3] + b1;
            *(float2*)(C + (size_t)r0*NTOT + n) = v0;
            *(float2*)(C + (size_t)(r0+8)*NTOT + n) = v1;
        }
    }
}

// ================= BN gather (layout [rows][64]) =================
template<int SEL>
__global__ void __launch_bounds__(256) k_bngather()
{
    const float* h = (SEL == 0) ? g_h2 : g_h3;
    constexpr int rows = (SEL == 0) ? 82944 : 50176;
    float* sum = (SEL == 0) ? g_bnacc       : g_bnacc + 128;
    float* sq  = (SEL == 0) ? g_bnacc + 64  : g_bnacc + 192;
    int gw = blockIdx.x*8 + (threadIdx.x >> 5);
    int lid = threadIdx.x & 31;
    int W = gridDim.x * 8;
    float s0 = 0.f, q0 = 0.f, s1 = 0.f, q1 = 0.f;
    for (int r = gw; r < rows; r += W) {
        float a = h[(size_t)r*64 + lid];
        float b = h[(size_t)r*64 + 32 + lid];
        s0 += a; q0 += a*a; s1 += b; q1 += b*b;
    }
    atomicAdd(&sum[lid], s0);      atomicAdd(&sq[lid], q0);
    atomicAdd(&sum[32+lid], s1);   atomicAdd(&sq[32+lid], q1);
}

// ================= LIF layer 2 (BN finalize inlined), planar, coalesced =================
__global__ void k_lif2(const float* __restrict__ gamma, const float* __restrict__ beta)
{
    int idx = blockIdx.x*blockDim.x + threadIdx.x;
    if (idx >= 128*81*64) return;
    int c = idx & 63;
    float m = g_bnacc[c] * (1.f/82944.f);
    float var = g_bnacc[64 + c] * (1.f/82944.f) - m*m;
    float sc = rsqrtf(var + 1e-5f) * gamma[c];
    float be = beta[c];
    float v = 0.f;
    #pragma unroll
    for (int t = 0; t < 8; t++) {
        float a = (g_h2[(size_t)t*663552 + idx] - m)*sc + be;
        v = v + (a - v)*0.5f;
        float s = (v >= 1.0f) ? 1.0f : 0.0f;
        g_s2b[(size_t)t*663552 + idx] = __float2bfloat16(s);
        v = v * (1.0f - s);
    }
}

// ================= LIF layer 3 (BN finalize inlined), planar =================
__global__ void k_lif3(const float* __restrict__ gamma, const float* __restrict__ beta)
{
    int idx = blockIdx.x*blockDim.x + threadIdx.x;
    if (idx >= 128*49*64) return;
    int c = idx & 63;
    float m = g_bnacc[128 + c] * (1.f/50176.f);
    float var = g_bnacc[192 + c] * (1.f/50176.f) - m*m;
    float sc = rsqrtf(var + 1e-5f) * gamma[c];
    float be = beta[c];
    float v = 0.f;
    #pragma unroll
    for (int t = 0; t < 8; t++) {
        float a = (g_h3[(size_t)t*401408 + idx] - m)*sc + be;
        v = v + (a - v)*0.5f;
        float s = (v >= 1.0f) ? 1.0f : 0.0f;
        g_s3b[(size_t)t*401408 + idx] = __float2bfloat16(s);
        v = v * (1.0f - s);
    }
}

// ================= tail: LIF4 + fco + mean over T, one block per batch =================
__global__ void __launch_bounds__(512) k_tail(const float* __restrict__ fb,
                                              const float* __restrict__ fco_w,
                                              const float* __restrict__ fco_b,
                                              float* __restrict__ out)
{
    __shared__ float s0[512], s1[512];
    int b = blockIdx.x, o = threadIdx.x;
    float bb = fb[o];
    float v = 0.f, cnt = 0.f;
    #pragma unroll
    for (int t = 0; t < 8; t++) {
        int j = (t*128 + b)*512 + o;
        float a = g_h4[j] + g_h4[524288 + j] + bb;
        v = v + (a - v)*0.5f;
        float s = (v >= 1.0f) ? 1.0f : 0.0f;
        cnt += s;
        v = v * (1.0f - s);
    }
    s0[o] = cnt * fco_w[o];
    s1[o] = cnt * fco_w[512 + o];
    __syncthreads();
    for (int k = 256; k > 0; k >>= 1) {
        if (o < k) { s0[o] += s0[o+k]; s1[o] += s1[o+k]; }
        __syncthreads();
    }
    if (o == 0) {
        out[b*2 + 0] = fco_b[0] + s0[0] * 0.125f;
        out[b*2 + 1] = fco_b[1] + s1[0] * 0.125f;
    }
}

// ================= launch =================
extern "C" void kernel_launch(void* const* d_in, const int* in_sizes, int n_in,
                              void* d_out, int out_size)
{
    const float* x   = (const float*)d_in[0];
    const float* c1w = (const float*)d_in[1];
    const float* c1b = (const float*)d_in[2];
    const float* g1  = (const float*)d_in[3];
    const float* b1  = (const float*)d_in[4];
    const float* c2w = (const float*)d_in[5];
    const float* c2b = (const float*)d_in[6];
    const float* g2  = (const float*)d_in[7];
    const float* b2  = (const float*)d_in[8];
    const float* c3w = (const float*)d_in[9];
    const float* c3b = (const float*)d_in[10];
    const float* g3  = (const float*)d_in[11];
    const float* b3  = (const float*)d_in[12];
    const float* fw  = (const float*)d_in[13];
    const float* fb  = (const float*)d_in[14];
    const float* ow  = (const float*)d_in[15];
    const float* ob  = (const float*)d_in[16];
    float* out = (float*)d_out;

    cudaFuncSetAttribute(k_conv1, cudaFuncAttributeMaxDynamicSharedMemorySize, SMEM1);

    k_zero<<<1, 256>>>();
    k_wsplit<0><<<64, 256>>>(c2w);
    k_wsplit<1><<<64, 256>>>(c3w);
    k_wsplit<2><<<512, 256>>>(fw);

    k_conv1<<<128, 256, SMEM1>>>(x, c1w, c1b);
    k_bnstats1<<<128, 256>>>();
    k_lif1<<<(1638400 + 255)/256, 256>>>(g1, b1);

    k_gemm<0><<<dim3(648, 1), 256>>>(c2b);
    k_bngather<0><<<256, 256>>>();
    k_lif2<<<(663552 + 255)/256, 256>>>(g2, b2);

    k_gemm<1><<<dim3(392, 1), 256>>>(c3b);
    k_bngather<1><<<128, 256>>>();
    k_lif3<<<(401408 + 255)/256, 256>>>(g3, b3);

    k_gemm<2><<<dim3(8, 8, 2), 256>>>(fb);
    k_tail<<<128, 512>>>(fb, ow, ob, out);
}

// round 11
// speedup vs baseline: 4.7827x; 1.0256x over previous
#include <cuda_runtime.h>
#include <cuda_bf16.h>
#include <cstdint>

// ================= scratch (device globals; no allocation allowed) =================
__device__ __align__(16) float g_h1[128*400*32];                  // conv1 out [b][pix][c]
__device__ __align__(16) __nv_bfloat16 g_s1b[8*128*400*32];       // spikes L1 [t][b][pix][c32]
__device__ __align__(16) float g_h2[82944*64];                    // conv2 out [tb*81+pos][c]
__device__ __align__(16) __nv_bfloat16 g_s2b[8*128*81*64];        // spikes L2 [tb][pos][c64]
__device__ __align__(16) float g_h3[50176*64];                    // conv3 out [tb*49+pos][c]
__device__ __align__(16) __nv_bfloat16 g_s3b[1024*3136];          // spikes L3 [tb][pos*64+c]
__device__ __align__(16) float g_h4[2*1024*512];                  // fc1 out (2 K-split partials)
__device__ float g_bnacc[256];    // [sum2(64)|sq2(64)|sum3(64)|sq3(64)]
__device__ float g_bn1acc[64];    // [sum1(32)|sq1(32)]
__device__ __align__(16) __nv_bfloat16 g_w2hi[64*512],  g_w2lo[64*512];
__device__ __align__(16) __nv_bfloat16 g_w3hi[64*576],  g_w3lo[64*576];
__device__ __align__(16) __nv_bfloat16 g_wfhi[512*3136], g_wflo[512*3136];

// ================= helpers =================
__device__ __forceinline__ uint32_t smem_u32(const void* p) {
    return (uint32_t)__cvta_generic_to_shared(p);
}
#define CP16(dst_u32, src_ptr) \
    asm volatile("cp.async.cg.shared.global [%0], [%1], 16;" :: "r"(dst_u32), "l"(src_ptr))
#define CP_COMMIT() asm volatile("cp.async.commit_group;" ::: "memory")
#define CP_WAIT(n)  asm volatile("cp.async.wait_group %0;" :: "n"(n) : "memory")

// ================= conv1 (fp32): [128,4,84,84] -> h1[b][pix(400)][c(32)] =================
#define SMEM1 ((28224 + 256*33)*4)
__global__ void __launch_bounds__(256) k_conv1(const float* __restrict__ x,
                                               const float* __restrict__ w,
                                               const float* __restrict__ bias)
{
    extern __shared__ float sm[];
    float* s_in = sm;
    float* s_w  = sm + 28224;
    const int n = blockIdx.x, tid = threadIdx.x;

    const float4* gx = (const float4*)(x + n*28224);
    for (int i = tid; i < 7056; i += 256) ((float4*)s_in)[i] = gx[i];
    for (int i = tid; i < 8192; i += 256) {
        int oc = i >> 8, tap = i & 255;
        s_w[tap*33 + oc] = w[i];
    }
    __syncthreads();

    for (int task = tid; task < 400; task += 256) {
        int ocg = task & 3, posg = task >> 2;
        int oc0 = ocg * 8, p0 = posg * 4;
        float acc[8][4];
        #pragma unroll
        for (int i = 0; i < 8; i++)
            #pragma unroll
            for (int j = 0; j < 4; j++) acc[i][j] = 0.f;
        int base[4];
        #pragma unroll
        for (int j = 0; j < 4; j++) {
            int p = p0 + j, oy = p / 20, ox = p - oy*20;
            base[j] = oy*4*84 + ox*4;
        }
        for (int ic = 0; ic < 4; ic++) {
            #pragma unroll
            for (int ky = 0; ky < 8; ky++) {
                int ib = ic*7056 + ky*84;
                const float* wrow = s_w + (ic*64 + ky*8)*33 + oc0;
                #pragma unroll
                for (int kx = 0; kx < 8; kx++) {
                    float in0 = s_in[base[0]+ib+kx];
                    float in1 = s_in[base[1]+ib+kx];
                    float in2 = s_in[base[2]+ib+kx];
                    float in3 = s_in[base[3]+ib+kx];
                    const float* wp = wrow + kx*33;
                    #pragma unroll
                    for (int i = 0; i < 8; i++) {
                        float wf = wp[i];
                        acc[i][0] += wf*in0; acc[i][1] += wf*in1;
                        acc[i][2] += wf*in2; acc[i][3] += wf*in3;
                    }
                }
            }
        }
        #pragma unroll
        for (int j = 0; j < 4; j++) {
            #pragma unroll
            for (int i = 0; i < 8; i++)
                g_h1[(n*400 + p0+j)*32 + oc0+i] = acc[i][j] + bias[oc0+i];
        }
    }
}

// ================= BN stats layer 1: gather over [b*pix rows][c32] =================
__global__ void __launch_bounds__(256) k_bnstats1()
{
    int gw = blockIdx.x*8 + (threadIdx.x >> 5);
    int lane = threadIdx.x & 31;
    int W = gridDim.x * 8;
    float s = 0.f, q = 0.f;
    for (int r = gw; r < 51200; r += W) {
        float v = g_h1[r*32 + lane];
        s += v; q += v*v;
    }
    atomicAdd(&g_bn1acc[lane], s);
    atomicAdd(&g_bn1acc[32 + lane], q);
}

// ================= LIF layer 1 (BN finalize inlined) -> bf16 spikes =================
__global__ void k_lif1(const float* __restrict__ gamma, const float* __restrict__ beta)
{
    int idx = blockIdx.x*blockDim.x + threadIdx.x;
    if (idx >= 128*400*32) return;
    int c = idx & 31;
    float m = g_bn1acc[c] * (1.f/51200.f);
    float var = g_bn1acc[32 + c] * (1.f/51200.f) - m*m;
    float a = (g_h1[idx] - m) * rsqrtf(var + 1e-5f) * gamma[c] + beta[c];
    float v = 0.f;
    #pragma unroll
    for (int t = 0; t < 8; t++) {
        v = v + (a - v)*0.5f;
        float s = (v >= 1.0f) ? 1.0f : 0.0f;
        g_s1b[t*1638400 + idx] = __float2bfloat16(s);
        v = v * (1.0f - s);
    }
}

// ================= weight split -> bf16 hi/lo, conflict-free, coalesced both sides ==========
// block per oc: stage src row (floats) coalesced in smem; output-major conversion:
// tap=i, read sfl[ic*KHW + kk] (smem stride KHW -> no/2-way conflicts); global writes coalesced.
template<int SEL>
__global__ void __launch_bounds__(256) k_wsplit(const float* __restrict__ src)
{
    constexpr int K   = (SEL == 0) ? 512 : (SEL == 1) ? 576 : 3136;
    constexpr int IC  = (SEL == 0) ? 32 : (SEL == 1) ? 64 : 64;
    constexpr int KHW = (SEL == 0) ? 16 : (SEL == 1) ? 9  : 49;
    __nv_bfloat16* hi = (SEL == 0) ? g_w2hi : (SEL == 1) ? g_w3hi : g_wfhi;
    __nv_bfloat16* lo = (SEL == 0) ? g_w2lo : (SEL == 1) ? g_w3lo : g_wflo;
    __shared__ float sfl[K];
    int oc = blockIdx.x, tid = threadIdx.x;
    const float* row = src + (size_t)oc*K;
    for (int i = tid; i < K; i += 256) sfl[i] = row[i];
    __syncthreads();
    __nv_bfloat16* dh = hi + (size_t)oc*K;
    __nv_bfloat16* dl = lo + (size_t)oc*K;
    for (int i = tid; i < K; i += 256) {
        int kk = i / IC, ic = i - kk*IC;
        float w = sfl[ic*KHW + kk];
        __nv_bfloat16 h = __float2bfloat16(w);
        dh[i] = h;
        dl[i] = __float2bfloat16(w - __bfloat162float(h));
    }
}

__global__ void k_zero()
{
    if (threadIdx.x < 256) g_bnacc[threadIdx.x] = 0.f;
    if (threadIdx.x < 64)  g_bn1acc[threadIdx.x] = 0.f;
}

// ================= bf16 mma.sync GEMM, 3-stage cp.async pipeline, implicit im2col A ==========
#define MMA_OP(d, a0,a1,a2,a3, b0,b1) \
    asm volatile("mma.sync.aligned.m16n8k16.row.col.f32.bf16.bf16.f32 " \
        "{%0,%1,%2,%3}, {%4,%5,%6,%7}, {%8,%9}, {%0,%1,%2,%3};" \
        : "+f"((d)[0]), "+f"((d)[1]), "+f"((d)[2]), "+f"((d)[3]) \
        : "r"(a0), "r"(a1), "r"(a2), "r"(a3), "r"(b0), "r"(b1))

template<int LAYER>
__global__ void __launch_bounds__(256) k_gemm(const float* __restrict__ bias)
{
    constexpr int K    = (LAYER == 0) ? 512 : (LAYER == 1) ? 576 : 3136;
    constexpr int NTOT = (LAYER == 2) ? 512 : 64;
    constexpr int NCH  = (LAYER == 0) ? 16 : (LAYER == 1) ? 18 : 49;
    const __nv_bfloat16* Asrc = (LAYER == 0) ? g_s1b : (LAYER == 1) ? g_s2b : g_s3b;
    const __nv_bfloat16* Bhi = (LAYER == 0) ? g_w2hi: (LAYER == 1) ? g_w3hi: g_wfhi;
    const __nv_bfloat16* Blo = (LAYER == 0) ? g_w2lo: (LAYER == 1) ? g_w3lo: g_wflo;
    float* C                 = (LAYER == 0) ? g_h2  : (LAYER == 1) ? g_h3
                                            : g_h4 + (size_t)blockIdx.z*524288;
    const int cbase = (LAYER == 2) ? blockIdx.z*49 : 0;

    __shared__ __align__(16) __nv_bfloat16 sA[3][128*40];
    __shared__ __align__(16) __nv_bfloat16 sBh[3][64*40];
    __shared__ __align__(16) __nv_bfloat16 sBl[3][64*40];

    const int tid = threadIdx.x;
    const int wid = tid >> 5, lane = tid & 31;
    const int gq = lane >> 2, q = lane & 3;
    const int wm = wid & 3, wn = wid >> 2;
    const int m0 = blockIdx.x * 128, n0 = blockIdx.y * 64;

    uint32_t uA[3]  = { smem_u32(sA[0]),  smem_u32(sA[1]),  smem_u32(sA[2]) };
    uint32_t uBh[3] = { smem_u32(sBh[0]), smem_u32(sBh[1]), smem_u32(sBh[2]) };
    uint32_t uBl[3] = { smem_u32(sBl[0]), smem_u32(sBl[1]), smem_u32(sBl[2]) };

    const int gg = tid & 3;
    size_t abase[2];
    uint32_t adst[2];
    #pragma unroll
    for (int it = 0; it < 2; it++) {
        int r = (tid >> 2) + it*64;
        int rg = m0 + r;
        if (LAYER == 0) {
            int tb = rg / 81, pos = rg - tb*81;
            int oy = pos / 9, ox = pos - oy*9;
            abase[it] = (size_t)tb*12800 + (size_t)(oy*40 + ox*2)*32 + gg*8;
        } else if (LAYER == 1) {
            int tb = rg / 49, pos = rg - tb*49;
            int oy = pos / 7, ox = pos - oy*7;
            abase[it] = (size_t)tb*5184 + (size_t)(oy*9 + ox)*64 + gg*8;
        } else {
            abase[it] = (size_t)rg*3136 + gg*8;
        }
        adst[it] = (uint32_t)(r*40 + gg*8)*2;
    }

    auto load_chunk = [&](int cc, int buf) {
        int aoff;
        if (LAYER == 0) {
            int ky = cc >> 2, kx = cc & 3;
            aoff = (ky*20 + kx)*32;
        } else if (LAYER == 1) {
            int kk = cc >> 1, half = cc & 1;
            int ky = kk / 3, kx = kk - ky*3;
            aoff = (ky*9 + kx)*64 + half*32;
        } else {
            aoff = (cbase + cc) << 5;
        }
        #pragma unroll
        for (int it = 0; it < 2; it++)
            CP16(uA[buf] + adst[it], Asrc + abase[it] + aoff);
        int k0 = (cbase + cc) << 5;
        int r = tid >> 2;
        CP16(uBh[buf] + (uint32_t)(r*40 + gg*8)*2, Bhi + (size_t)(n0 + r)*K + k0 + gg*8);
        CP16(uBl[buf] + (uint32_t)(r*40 + gg*8)*2, Blo + (size_t)(n0 + r)*K + k0 + gg*8);
    };

    float acc[2][4][4];
    #pragma unroll
    for (int mi = 0; mi < 2; mi++)
        #pragma unroll
        for (int nt = 0; nt < 4; nt++)
            #pragma unroll
            for (int j = 0; j < 4; j++) acc[mi][nt][j] = 0.f;

    load_chunk(0, 0); CP_COMMIT();
    load_chunk(1, 1); CP_COMMIT();

    for (int c = 0; c < NCH; c++) {
        int buf = c % 3;
        if (c + 1 < NCH) CP_WAIT(1); else CP_WAIT(0);
        __syncthreads();

        const uint32_t* wA  = (const uint32_t*)sA[buf];
        const uint32_t* wBh = (const uint32_t*)sBh[buf];
        const uint32_t* wBl = (const uint32_t*)sBl[buf];
        #pragma unroll
        for (int ks = 0; ks < 2; ks++) {
            int kw = ks * 8;
            uint32_t a[2][4];
            #pragma unroll
            for (int mi = 0; mi < 2; mi++) {
                int r0 = wm*32 + mi*16 + gq;
                a[mi][0] = wA[r0*20 + kw + q];
                a[mi][1] = wA[(r0+8)*20 + kw + q];
                a[mi][2] = wA[r0*20 + kw + 4 + q];
                a[mi][3] = wA[(r0+8)*20 + kw + 4 + q];
            }
            #pragma unroll
            for (int nt = 0; nt < 4; nt++) {
                int n = wn*32 + nt*8 + gq;
                uint32_t bh0 = wBh[n*20 + kw + q];
                uint32_t bh1 = wBh[n*20 + kw + 4 + q];
                MMA_OP(acc[0][nt], a[0][0],a[0][1],a[0][2],a[0][3], bh0, bh1);
                MMA_OP(acc[1][nt], a[1][0],a[1][1],a[1][2],a[1][3], bh0, bh1);
                uint32_t bl0 = wBl[n*20 + kw + q];
                uint32_t bl1 = wBl[n*20 + kw + 4 + q];
                MMA_OP(acc[0][nt], a[0][0],a[0][1],a[0][2],a[0][3], bl0, bl1);
                MMA_OP(acc[1][nt], a[1][0],a[1][1],a[1][2],a[1][3], bl0, bl1);
            }
        }
        __syncthreads();
        if (c + 2 < NCH) { load_chunk(c + 2, (c + 2) % 3); CP_COMMIT(); }
    }

    #pragma unroll
    for (int mi = 0; mi < 2; mi++) {
        int r0 = m0 + wm*32 + mi*16 + gq;
        #pragma unroll
        for (int nt = 0; nt < 4; nt++) {
            int n = n0 + wn*32 + nt*8 + q*2;
            float b0 = 0.f, b1 = 0.f;
            if (LAYER != 2) { b0 = bias[n]; b1 = bias[n+1]; }
            float2 v0; v0.x = acc[mi][nt][0] + b0; v0.y = acc[mi][nt][1] + b1;
            float2 v1; v1.x = acc[mi][nt][2] + b0; v1.y = acc[mi][nt][3] + b1;
            *(float2*)(C + (size_t)r0*NTOT + n) = v0;
            *(float2*)(C + (size_t)(r0+8)*NTOT + n) = v1;
        }
    }
}

// ================= BN gather (layout [rows][64]) =================
template<int SEL>
__global__ void __launch_bounds__(256) k_bngather()
{
    const float* h = (SEL == 0) ? g_h2 : g_h3;
    constexpr int rows = (SEL == 0) ? 82944 : 50176;
    float* sum = (SEL == 0) ? g_bnacc       : g_bnacc + 128;
    float* sq  = (SEL == 0) ? g_bnacc + 64  : g_bnacc + 192;
    int gw = blockIdx.x*8 + (threadIdx.x >> 5);
    int lid = threadIdx.x & 31;
    int W = gridDim.x * 8;
    float s0 = 0.f, q0 = 0.f, s1 = 0.f, q1 = 0.f;
    for (int r = gw; r < rows; r += W) {
        float a = h[(size_t)r*64 + lid];
        float b = h[(size_t)r*64 + 32 + lid];
        s0 += a; q0 += a*a; s1 += b; q1 += b*b;
    }
    atomicAdd(&sum[lid], s0);      atomicAdd(&sq[lid], q0);
    atomicAdd(&sum[32+lid], s1);   atomicAdd(&sq[32+lid], q1);
}

// ================= LIF layer 2 (BN finalize inlined), planar, coalesced =================
__global__ void k_lif2(const float* __restrict__ gamma, const float* __restrict__ beta)
{
    int idx = blockIdx.x*blockDim.x + threadIdx.x;
    if (idx >= 128*81*64) return;
    int c = idx & 63;
    float m = g_bnacc[c] * (1.f/82944.f);
    float var = g_bnacc[64 + c] * (1.f/82944.f) - m*m;
    float sc = rsqrtf(var + 1e-5f) * gamma[c];
    float be = beta[c];
    float v = 0.f;
    #pragma unroll
    for (int t = 0; t < 8; t++) {
        float a = (g_h2[(size_t)t*663552 + idx] - m)*sc + be;
        v = v + (a - v)*0.5f;
        float s = (v >= 1.0f) ? 1.0f : 0.0f;
        g_s2b[(size_t)t*663552 + idx] = __float2bfloat16(s);
        v = v * (1.0f - s);
    }
}

// ================= LIF layer 3 (BN finalize inlined), planar =================
__global__ void k_lif3(const float* __restrict__ gamma, const float* __restrict__ beta)
{
    int idx = blockIdx.x*blockDim.x + threadIdx.x;
    if (idx >= 128*49*64) return;
    int c = idx & 63;
    float m = g_bnacc[128 + c] * (1.f/50176.f);
    float var = g_bnacc[192 + c] * (1.f/50176.f) - m*m;
    float sc = rsqrtf(var + 1e-5f) * gamma[c];
    float be = beta[c];
    float v = 0.f;
    #pragma unroll
    for (int t = 0; t < 8; t++) {
        float a = (g_h3[(size_t)t*401408 + idx] - m)*sc + be;
        v = v + (a - v)*0.5f;
        float s = (v >= 1.0f) ? 1.0f : 0.0f;
        g_s3b[(size_t)t*401408 + idx] = __float2bfloat16(s);
        v = v * (1.0f - s);
    }
}

// ================= tail: LIF4 + fco + mean over T, one block per batch =================
__global__ void __launch_bounds__(512) k_tail(const float* __restrict__ fb,
                                              const float* __restrict__ fco_w,
                                              const float* __restrict__ fco_b,
                                              float* __restrict__ out)
{
    __shared__ float s0[512], s1[512];
    int b = blockIdx.x, o = threadIdx.x;
    float bb = fb[o];
    float v = 0.f, cnt = 0.f;
    #pragma unroll
    for (int t = 0; t < 8; t++) {
        int j = (t*128 + b)*512 + o;
        float a = g_h4[j] + g_h4[524288 + j] + bb;
        v = v + (a - v)*0.5f;
        float s = (v >= 1.0f) ? 1.0f : 0.0f;
        cnt += s;
        v = v * (1.0f - s);
    }
    s0[o] = cnt * fco_w[o];
    s1[o] = cnt * fco_w[512 + o];
    __syncthreads();
    for (int k = 256; k > 0; k >>= 1) {
        if (o < k) { s0[o] += s0[o+k]; s1[o] += s1[o+k]; }
        __syncthreads();
    }
    if (o == 0) {
        out[b*2 + 0] = fco_b[0] + s0[0] * 0.125f;
        out[b*2 + 1] = fco_b[1] + s1[0] * 0.125f;
    }
}

// ================= launch =================
extern "C" void kernel_launch(void* const* d_in, const int* in_sizes, int n_in,
                              void* d_out, int out_size)
{
    const float* x   = (const float*)d_in[0];
    const float* c1w = (const float*)d_in[1];
    const float* c1b = (const float*)d_in[2];
    const float* g1  = (const float*)d_in[3];
    const float* b1  = (const float*)d_in[4];
    const float* c2w = (const float*)d_in[5];
    const float* c2b = (const float*)d_in[6];
    const float* g2  = (const float*)d_in[7];
    const float* b2  = (const float*)d_in[8];
    const float* c3w = (const float*)d_in[9];
    const float* c3b = (const float*)d_in[10];
    const float* g3  = (const float*)d_in[11];
    const float* b3  = (const float*)d_in[12];
    const float* fw  = (const float*)d_in[13];
    const float* fb  = (const float*)d_in[14];
    const float* ow  = (const float*)d_in[15];
    const float* ob  = (const float*)d_in[16];
    float* out = (float*)d_out;

    cudaFuncSetAttribute(k_conv1, cudaFuncAttributeMaxDynamicSharedMemorySize, SMEM1);

    k_zero<<<1, 256>>>();
    k_wsplit<0><<<64, 256>>>(c2w);
    k_wsplit<1><<<64, 256>>>(c3w);
    k_wsplit<2><<<512, 256>>>(fw);

    k_conv1<<<128, 256, SMEM1>>>(x, c1w, c1b);
    k_bnstats1<<<128, 256>>>();
    k_lif1<<<(1638400 + 255)/256, 256>>>(g1, b1);

    k_gemm<0><<<dim3(648, 1), 256>>>(c2b);
    k_bngather<0><<<256, 256>>>();
    k_lif2<<<(663552 + 255)/256, 256>>>(g2, b2);

    k_gemm<1><<<dim3(392, 1), 256>>>(c3b);
    k_bngather<1><<<128, 256>>>();
    k_lif3<<<(401408 + 255)/256, 256>>>(g3, b3);

    k_gemm<2><<<dim3(8, 8, 2), 256>>>(fb);
    k_tail<<<128, 512>>>(fb, ow, ob, out);
}

// round 13
// speedup vs baseline: 5.4876x; 1.1474x over previous
#include <cuda_runtime.h>
#include <cuda_bf16.h>
#include <cstdint>

// ================= scratch (device globals; no allocation allowed) =================
__device__ __align__(16) float g_h1[128*400*32];                  // conv1 out [b][pix][c]
__device__ __align__(16) __nv_bfloat16 g_s1b[8*128*400*32];       // spikes L1 [t][b][pix][c32]
__device__ __align__(16) float g_h2[82944*64];                    // conv2 out [tb*81+pos][c]
__device__ __align__(16) __nv_bfloat16 g_s2b[8*128*81*64];        // spikes L2 [tb][pos][c64]
__device__ __align__(16) float g_h3[50176*64];                    // conv3 out [tb*49+pos][c]
__device__ __align__(16) __nv_bfloat16 g_s3b[1024*3136];          // spikes L3 [tb][pos*64+c]
__device__ __align__(16) float g_h4[2*1024*512];                  // fc1 out (2 K-split partials)
__device__ float g_bnacc[256];    // [sum2(64)|sq2(64)|sum3(64)|sq3(64)]
__device__ float g_bn1acc[64];    // [sum1(32)|sq1(32)]
__device__ __align__(16) __nv_bfloat16 g_w2hi[64*512],  g_w2lo[64*512];
__device__ __align__(16) __nv_bfloat16 g_w3hi[64*576],  g_w3lo[64*576];
__device__ __align__(16) __nv_bfloat16 g_wfhi[512*3136], g_wflo[512*3136];

// ================= helpers =================
__device__ __forceinline__ uint32_t smem_u32(const void* p) {
    return (uint32_t)__cvta_generic_to_shared(p);
}
#define CP16(dst_u32, src_ptr) \
    asm volatile("cp.async.cg.shared.global [%0], [%1], 16;" :: "r"(dst_u32), "l"(src_ptr))
#define CP_COMMIT() asm volatile("cp.async.commit_group;" ::: "memory")
#define CP_WAIT(n)  asm volatile("cp.async.wait_group %0;" :: "n"(n) : "memory")

// ================= conv1 + fused BN1 stats: [128,4,84,84] -> h1[b][pix(400)][c(32)] =====
#define SMEM1 ((28224 + 256*33)*4)
__global__ void __launch_bounds__(256) k_conv1(const float* __restrict__ x,
                                               const float* __restrict__ w,
                                               const float* __restrict__ bias)
{
    extern __shared__ float sm[];
    float* s_in = sm;
    float* s_w  = sm + 28224;
    __shared__ float s_sum[32], s_sq[32];
    const int n = blockIdx.x, tid = threadIdx.x;
    const int lane = tid & 31;

    const float4* gx = (const float4*)(x + n*28224);
    for (int i = tid; i < 7056; i += 256) ((float4*)s_in)[i] = gx[i];
    for (int i = tid; i < 8192; i += 256) {
        int oc = i >> 8, tap = i & 255;
        s_w[tap*33 + oc] = w[i];
    }
    if (tid < 32) { s_sum[tid] = 0.f; s_sq[tid] = 0.f; }
    __syncthreads();

    float ch_sum[8], ch_sq[8];
    #pragma unroll
    for (int i = 0; i < 8; i++) { ch_sum[i] = 0.f; ch_sq[i] = 0.f; }

    for (int task = tid; task < 400; task += 256) {
        int ocg = task & 3, posg = task >> 2;    // ocg == tid&3 always (256 % 4 == 0)
        int oc0 = ocg * 8, p0 = posg * 4;
        float acc[8][4];
        #pragma unroll
        for (int i = 0; i < 8; i++)
            #pragma unroll
            for (int j = 0; j < 4; j++) acc[i][j] = 0.f;
        int base[4];
        #pragma unroll
        for (int j = 0; j < 4; j++) {
            int p = p0 + j, oy = p / 20, ox = p - oy*20;
            base[j] = oy*4*84 + ox*4;
        }
        for (int ic = 0; ic < 4; ic++) {
            #pragma unroll
            for (int ky = 0; ky < 8; ky++) {
                int ib = ic*7056 + ky*84;
                const float* wrow = s_w + (ic*64 + ky*8)*33 + oc0;
                #pragma unroll
                for (int kx = 0; kx < 8; kx++) {
                    float in0 = s_in[base[0]+ib+kx];
                    float in1 = s_in[base[1]+ib+kx];
                    float in2 = s_in[base[2]+ib+kx];
                    float in3 = s_in[base[3]+ib+kx];
                    const float* wp = wrow + kx*33;
                    #pragma unroll
                    for (int i = 0; i < 8; i++) {
                        float wf = wp[i];
                        acc[i][0] += wf*in0; acc[i][1] += wf*in1;
                        acc[i][2] += wf*in2; acc[i][3] += wf*in3;
                    }
                }
            }
        }
        #pragma unroll
        for (int j = 0; j < 4; j++) {
            #pragma unroll
            for (int i = 0; i < 8; i++) {
                float val = acc[i][j] + bias[oc0+i];
                g_h1[(n*400 + p0+j)*32 + oc0+i] = val;
                ch_sum[i] += val; ch_sq[i] += val*val;
            }
        }
    }

    // reduce over lanes with same (lane&3) (strides 16,8,4) -> lanes 0..3 hold ocg totals
    #pragma unroll
    for (int s = 16; s >= 4; s >>= 1) {
        #pragma unroll
        for (int i = 0; i < 8; i++) {
            ch_sum[i] += __shfl_down_sync(0xffffffffu, ch_sum[i], s);
            ch_sq[i]  += __shfl_down_sync(0xffffffffu, ch_sq[i],  s);
        }
    }
    if (lane < 4) {
        #pragma unroll
        for (int i = 0; i < 8; i++) {
            atomicAdd(&s_sum[lane*8 + i], ch_sum[i]);
            atomicAdd(&s_sq[lane*8 + i],  ch_sq[i]);
        }
    }
    __syncthreads();
    if (tid < 32)       atomicAdd(&g_bn1acc[tid], s_sum[tid]);
    else if (tid < 64)  atomicAdd(&g_bn1acc[tid], s_sq[tid - 32]);
}

// ================= LIF layer 1 (BN finalize inlined) -> bf16 spikes =================
__global__ void k_lif1(const float* __restrict__ gamma, const float* __restrict__ beta)
{
    int idx = blockIdx.x*blockDim.x + threadIdx.x;
    if (idx >= 128*400*32) return;
    int c = idx & 31;
    float m = g_bn1acc[c] * (1.f/51200.f);
    float var = g_bn1acc[32 + c] * (1.f/51200.f) - m*m;
    float a = (g_h1[idx] - m) * rsqrtf(var + 1e-5f) * gamma[c] + beta[c];
    float v = 0.f;
    #pragma unroll
    for (int t = 0; t < 8; t++) {
        v = v + (a - v)*0.5f;
        float s = (v >= 1.0f) ? 1.0f : 0.0f;
        g_s1b[t*1638400 + idx] = __float2bfloat16(s);
        v = v * (1.0f - s);
    }
}

// ================= combined weight split (all 3 layers) + BN accumulator zeroing ==========
template<int SEL>
__device__ __forceinline__ void wsplit_body(const float* __restrict__ src, int oc)
{
    constexpr int K   = (SEL == 0) ? 512 : (SEL == 1) ? 576 : 3136;
    constexpr int IC  = (SEL == 0) ? 32 : (SEL == 1) ? 64 : 64;
    constexpr int KHW = (SEL == 0) ? 16 : (SEL == 1) ? 9  : 49;
    __nv_bfloat16* hi = (SEL == 0) ? g_w2hi : (SEL == 1) ? g_w3hi : g_wfhi;
    __nv_bfloat16* lo = (SEL == 0) ? g_w2lo : (SEL == 1) ? g_w3lo : g_wflo;
    __shared__ float sfl[K];
    int tid = threadIdx.x;
    const float* row = src + (size_t)oc*K;
    for (int i = tid; i < K; i += 256) sfl[i] = row[i];
    __syncthreads();
    __nv_bfloat16* dh = hi + (size_t)oc*K;
    __nv_bfloat16* dl = lo + (size_t)oc*K;
    for (int i = tid; i < K; i += 256) {
        int kk = i / IC, ic = i - kk*IC;
        float w = sfl[ic*KHW + kk];
        __nv_bfloat16 h = __float2bfloat16(w);
        dh[i] = h;
        dl[i] = __float2bfloat16(w - __bfloat162float(h));
    }
}

__global__ void __launch_bounds__(256) k_wsplit_all(const float* __restrict__ w2,
                                                    const float* __restrict__ w3,
                                                    const float* __restrict__ wf)
{
    int b = blockIdx.x;
    if (b == 0) {   // zero BN accumulators (stream order guarantees visibility to later kernels)
        g_bnacc[threadIdx.x] = 0.f;
        if (threadIdx.x < 64) g_bn1acc[threadIdx.x] = 0.f;
    }
    if (b < 64)        wsplit_body<0>(w2, b);
    else if (b < 128)  wsplit_body<1>(w3, b - 64);
    else               wsplit_body<2>(wf, b - 128);
}

// ================= bf16 mma.sync GEMM, 3-stage cp.async, implicit im2col A, fused BN ==========
#define MMA_OP(d, a0,a1,a2,a3, b0,b1) \
    asm volatile("mma.sync.aligned.m16n8k16.row.col.f32.bf16.bf16.f32 " \
        "{%0,%1,%2,%3}, {%4,%5,%6,%7}, {%8,%9}, {%0,%1,%2,%3};" \
        : "+f"((d)[0]), "+f"((d)[1]), "+f"((d)[2]), "+f"((d)[3]) \
        : "r"(a0), "r"(a1), "r"(a2), "r"(a3), "r"(b0), "r"(b1))

template<int LAYER>
__global__ void __launch_bounds__(256) k_gemm(const float* __restrict__ bias)
{
    constexpr int K    = (LAYER == 0) ? 512 : (LAYER == 1) ? 576 : 3136;
    constexpr int NTOT = (LAYER == 2) ? 512 : 64;
    constexpr int NCH  = (LAYER == 0) ? 16 : (LAYER == 1) ? 18 : 49;
    const __nv_bfloat16* Asrc = (LAYER == 0) ? g_s1b : (LAYER == 1) ? g_s2b : g_s3b;
    const __nv_bfloat16* Bhi = (LAYER == 0) ? g_w2hi: (LAYER == 1) ? g_w3hi: g_wfhi;
    const __nv_bfloat16* Blo = (LAYER == 0) ? g_w2lo: (LAYER == 1) ? g_w3lo: g_wflo;
    float* C                 = (LAYER == 0) ? g_h2  : (LAYER == 1) ? g_h3
                                            : g_h4 + (size_t)blockIdx.z*524288;
    const int cbase = (LAYER == 2) ? blockIdx.z*49 : 0;

    __shared__ __align__(16) __nv_bfloat16 sA[3][128*40];
    __shared__ __align__(16) __nv_bfloat16 sBh[3][64*40];
    __shared__ __align__(16) __nv_bfloat16 sBl[3][64*40];
    __shared__ float bs[64], bq[64];

    const int tid = threadIdx.x;
    const int wid = tid >> 5, lane = tid & 31;
    const int gq = lane >> 2, q = lane & 3;
    const int wm = wid & 3, wn = wid >> 2;
    const int m0 = blockIdx.x * 128, n0 = blockIdx.y * 64;

    uint32_t uA[3]  = { smem_u32(sA[0]),  smem_u32(sA[1]),  smem_u32(sA[2]) };
    uint32_t uBh[3] = { smem_u32(sBh[0]), smem_u32(sBh[1]), smem_u32(sBh[2]) };
    uint32_t uBl[3] = { smem_u32(sBl[0]), smem_u32(sBl[1]), smem_u32(sBl[2]) };

    if (LAYER != 2 && tid < 64) { bs[tid] = 0.f; bq[tid] = 0.f; }

    const int gg = tid & 3;
    size_t abase[2];
    uint32_t adst[2];
    #pragma unroll
    for (int it = 0; it < 2; it++) {
        int r = (tid >> 2) + it*64;
        int rg = m0 + r;
        if (LAYER == 0) {
            int tb = rg / 81, pos = rg - tb*81;
            int oy = pos / 9, ox = pos - oy*9;
            abase[it] = (size_t)tb*12800 + (size_t)(oy*40 + ox*2)*32 + gg*8;
        } else if (LAYER == 1) {
            int tb = rg / 49, pos = rg - tb*49;
            int oy = pos / 7, ox = pos - oy*7;
            abase[it] = (size_t)tb*5184 + (size_t)(oy*9 + ox)*64 + gg*8;
        } else {
            abase[it] = (size_t)rg*3136 + gg*8;
        }
        adst[it] = (uint32_t)(r*40 + gg*8)*2;
    }

    auto load_chunk = [&](int cc, int buf) {
        int aoff;
        if (LAYER == 0) {
            int ky = cc >> 2, kx = cc & 3;
            aoff = (ky*20 + kx)*32;
        } else if (LAYER == 1) {
            int kk = cc >> 1, half = cc & 1;
            int ky = kk / 3, kx = kk - ky*3;
            aoff = (ky*9 + kx)*64 + half*32;
        } else {
            aoff = (cbase + cc) << 5;
        }
        #pragma unroll
        for (int it = 0; it < 2; it++)
            CP16(uA[buf] + adst[it], Asrc + abase[it] + aoff);
        int k0 = (cbase + cc) << 5;
        int r = tid >> 2;
        CP16(uBh[buf] + (uint32_t)(r*40 + gg*8)*2, Bhi + (size_t)(n0 + r)*K + k0 + gg*8);
        CP16(uBl[buf] + (uint32_t)(r*40 + gg*8)*2, Blo + (size_t)(n0 + r)*K + k0 + gg*8);
    };

    float acc[2][4][4];
    #pragma unroll
    for (int mi = 0; mi < 2; mi++)
        #pragma unroll
        for (int nt = 0; nt < 4; nt++)
            #pragma unroll
            for (int j = 0; j < 4; j++) acc[mi][nt][j] = 0.f;

    load_chunk(0, 0); CP_COMMIT();
    load_chunk(1, 1); CP_COMMIT();

    for (int c = 0; c < NCH; c++) {
        int buf = c % 3;
        if (c + 1 < NCH) CP_WAIT(1); else CP_WAIT(0);
        __syncthreads();

        const uint32_t* wA  = (const uint32_t*)sA[buf];
        const uint32_t* wBh = (const uint32_t*)sBh[buf];
        const uint32_t* wBl = (const uint32_t*)sBl[buf];
        #pragma unroll
        for (int ks = 0; ks < 2; ks++) {
            int kw = ks * 8;
            uint32_t a[2][4];
            #pragma unroll
            for (int mi = 0; mi < 2; mi++) {
                int r0 = wm*32 + mi*16 + gq;
                a[mi][0] = wA[r0*20 + kw + q];
                a[mi][1] = wA[(r0+8)*20 + kw + q];
                a[mi][2] = wA[r0*20 + kw + 4 + q];
                a[mi][3] = wA[(r0+8)*20 + kw + 4 + q];
            }
            #pragma unroll
            for (int nt = 0; nt < 4; nt++) {
                int n = wn*32 + nt*8 + gq;
                uint32_t bh0 = wBh[n*20 + kw + q];
                uint32_t bh1 = wBh[n*20 + kw + 4 + q];
                MMA_OP(acc[0][nt], a[0][0],a[0][1],a[0][2],a[0][3], bh0, bh1);
                MMA_OP(acc[1][nt], a[1][0],a[1][1],a[1][2],a[1][3], bh0, bh1);
                uint32_t bl0 = wBl[n*20 + kw + q];
                uint32_t bl1 = wBl[n*20 + kw + 4 + q];
                MMA_OP(acc[0][nt], a[0][0],a[0][1],a[0][2],a[0][3], bl0, bl1);
                MMA_OP(acc[1][nt], a[1][0],a[1][1],a[1][2],a[1][3], bl0, bl1);
            }
        }
        __syncthreads();
        if (c + 2 < NCH) { load_chunk(c + 2, (c + 2) % 3); CP_COMMIT(); }
    }

    // epilogue: store + fused BN column sums (LAYER 0/1)
    float csum[4][2], csq[4][2];
    #pragma unroll
    for (int nt = 0; nt < 4; nt++) { csum[nt][0]=0.f; csum[nt][1]=0.f; csq[nt][0]=0.f; csq[nt][1]=0.f; }

    #pragma unroll
    for (int mi = 0; mi < 2; mi++) {
        int r0 = m0 + wm*32 + mi*16 + gq;
        #pragma unroll
        for (int nt = 0; nt < 4; nt++) {
            int n = n0 + wn*32 + nt*8 + q*2;
            float b0 = 0.f, b1 = 0.f;
            if (LAYER != 2) { b0 = bias[n]; b1 = bias[n+1]; }
            float v00 = acc[mi][nt][0] + b0, v01 = acc[mi][nt][1] + b1;
            float v10 = acc[mi][nt][2] + b0, v11 = acc[mi][nt][3] + b1;
            float2 w0; w0.x = v00; w0.y = v01;
            float2 w1; w1.x = v10; w1.y = v11;
            *(float2*)(C + (size_t)r0*NTOT + n) = w0;
            *(float2*)(C + (size_t)(r0+8)*NTOT + n) = w1;
            if (LAYER != 2) {
                csum[nt][0] += v00 + v10;  csq[nt][0] += v00*v00 + v10*v10;
                csum[nt][1] += v01 + v11;  csq[nt][1] += v01*v01 + v11*v11;
            }
        }
    }

    if (LAYER != 2) {
        #pragma unroll
        for (int s = 16; s >= 4; s >>= 1) {
            #pragma unroll
            for (int nt = 0; nt < 4; nt++) {
                csum[nt][0] += __shfl_down_sync(0xffffffffu, csum[nt][0], s);
                csum[nt][1] += __shfl_down_sync(0xffffffffu, csum[nt][1], s);
                csq[nt][0]  += __shfl_down_sync(0xffffffffu, csq[nt][0],  s);
                csq[nt][1]  += __shfl_down_sync(0xffffffffu, csq[nt][1],  s);
            }
        }
        __syncthreads();   // bs/bq zeroed earlier; all warps done with csum
        if (gq == 0) {
            #pragma unroll
            for (int nt = 0; nt < 4; nt++) {
                int co = wn*32 + nt*8 + q*2;
                atomicAdd(&bs[co],   csum[nt][0]);
                atomicAdd(&bs[co+1], csum[nt][1]);
                atomicAdd(&bq[co],   csq[nt][0]);
                atomicAdd(&bq[co+1], csq[nt][1]);
            }
        }
        __syncthreads();
        float* gsum = (LAYER == 0) ? g_bnacc      : g_bnacc + 128;
        float* gsq  = (LAYER == 0) ? g_bnacc + 64 : g_bnacc + 192;
        if (tid < 64)        atomicAdd(&gsum[tid], bs[tid]);
        else if (tid < 128)  atomicAdd(&gsq[tid-64], bq[tid-64]);
    }
}

// ================= LIF layer 2 (BN finalize inlined), planar, coalesced =================
__global__ void k_lif2(const float* __restrict__ gamma, const float* __restrict__ beta)
{
    int idx = blockIdx.x*blockDim.x + threadIdx.x;
    if (idx >= 128*81*64) return;
    int c = idx & 63;
    float m = g_bnacc[c] * (1.f/82944.f);
    float var = g_bnacc[64 + c] * (1.f/82944.f) - m*m;
    float sc = rsqrtf(var + 1e-5f) * gamma[c];
    float be = beta[c];
    float v = 0.f;
    #pragma unroll
    for (int t = 0; t < 8; t++) {
        float a = (g_h2[(size_t)t*663552 + idx] - m)*sc + be;
        v = v + (a - v)*0.5f;
        float s = (v >= 1.0f) ? 1.0f : 0.0f;
        g_s2b[(size_t)t*663552 + idx] = __float2bfloat16(s);
        v = v * (1.0f - s);
    }
}

// ================= LIF layer 3 (BN finalize inlined), planar =================
__global__ void k_lif3(const float* __restrict__ gamma, const float* __restrict__ beta)
{
    int idx = blockIdx.x*blockDim.x + threadIdx.x;
    if (idx >= 128*49*64) return;
    int c = idx & 63;
    float m = g_bnacc[128 + c] * (1.f/50176.f);
    float var = g_bnacc[192 + c] * (1.f/50176.f) - m*m;
    float sc = rsqrtf(var + 1e-5f) * gamma[c];
    float be = beta[c];
    float v = 0.f;
    #pragma unroll
    for (int t = 0; t < 8; t++) {
        float a = (g_h3[(size_t)t*401408 + idx] - m)*sc + be;
        v = v + (a - v)*0.5f;
        float s = (v >= 1.0f) ? 1.0f : 0.0f;
        g_s3b[(size_t)t*401408 + idx] = __float2bfloat16(s);
        v = v * (1.0f - s);
    }
}

// ================= tail: LIF4 + fco + mean over T, one block per batch =================
__global__ void __launch_bounds__(512) k_tail(const float* __restrict__ fb,
                                              const float* __restrict__ fco_w,
                                              const float* __restrict__ fco_b,
                                              float* __restrict__ out)
{
    __shared__ float s0[512], s1[512];
    int b = blockIdx.x, o = threadIdx.x;
    float bb = fb[o];
    float v = 0.f, cnt = 0.f;
    #pragma unroll
    for (int t = 0; t < 8; t++) {
        int j = (t*128 + b)*512 + o;
        float a = g_h4[j] + g_h4[524288 + j] + bb;
        v = v + (a - v)*0.5f;
        float s = (v >= 1.0f) ? 1.0f : 0.0f;
        cnt += s;
        v = v * (1.0f - s);
    }
    s0[o] = cnt * fco_w[o];
    s1[o] = cnt * fco_w[512 + o];
    __syncthreads();
    for (int k = 256; k > 0; k >>= 1) {
        if (o < k) { s0[o] += s0[o+k]; s1[o] += s1[o+k]; }
        __syncthreads();
    }
    if (o == 0) {
        out[b*2 + 0] = fco_b[0] + s0[0] * 0.125f;
        out[b*2 + 1] = fco_b[1] + s1[0] * 0.125f;
    }
}

// ================= launch =================
extern "C" void kernel_launch(void* const* d_in, const int* in_sizes, int n_in,
                              void* d_out, int out_size)
{
    const float* x   = (const float*)d_in[0];
    const float* c1w = (const float*)d_in[1];
    const float* c1b = (const float*)d_in[2];
    const float* g1  = (const float*)d_in[3];
    const float* b1  = (const float*)d_in[4];
    const float* c2w = (const float*)d_in[5];
    const float* c2b = (const float*)d_in[6];
    const float* g2  = (const float*)d_in[7];
    const float* b2  = (const float*)d_in[8];
    const float* c3w = (const float*)d_in[9];
    const float* c3b = (const float*)d_in[10];
    const float* g3  = (const float*)d_in[11];
    const float* b3  = (const float*)d_in[12];
    const float* fw  = (const float*)d_in[13];
    const float* fb  = (const float*)d_in[14];
    const float* ow  = (const float*)d_in[15];
    const float* ob  = (const float*)d_in[16];
    float* out = (float*)d_out;

    cudaFuncSetAttribute(k_conv1, cudaFuncAttributeMaxDynamicSharedMemorySize, SMEM1);

    k_wsplit_all<<<640, 256>>>(c2w, c3w, fw);

    k_conv1<<<128, 256, SMEM1>>>(x, c1w, c1b);
    k_lif1<<<(1638400 + 255)/256, 256>>>(g1, b1);

    k_gemm<0><<<dim3(648, 1), 256>>>(c2b);
    k_lif2<<<(663552 + 255)/256, 256>>>(g2, b2);

    k_gemm<1><<<dim3(392, 1), 256>>>(c3b);
    k_lif3<<<(401408 + 255)/256, 256>>>(g3, b3);

    k_gemm<2><<<dim3(8, 8, 2), 256>>>(fb);
    k_tail<<<128, 512>>>(fb, ow, ob, out);
}

// round 16
// speedup vs baseline: 5.8691x; 1.0695x over previous
#include <cuda_runtime.h>
#include <cuda_bf16.h>
#include <cstdint>

// ================= scratch (device globals; no allocation allowed) =================
__device__ __align__(16) float g_h1[128*400*32];                  // conv1 out [b][pix][c]
__device__ __align__(16) __nv_bfloat16 g_s1b[8*128*400*32];       // spikes L1 [t][b][pix][c32]
__device__ __align__(16) float g_h2[82944*64];                    // conv2 out [tb*81+pos][c]
__device__ __align__(16) __nv_bfloat16 g_s2b[8*128*81*64];        // spikes L2 [tb][pos][c64]
__device__ __align__(16) float g_h3[50176*64];                    // conv3 out [tb*49+pos][c]
__device__ __align__(16) __nv_bfloat16 g_s3b[1024*3136];          // spikes L3 [tb][pos*64+c]
__device__ __align__(16) float g_h4[2*1024*512];                  // fc1 out (2 K-split partials)
__device__ float g_bnacc[256];    // [sum2(64)|sq2(64)|sum3(64)|sq3(64)]
__device__ float g_bn1acc[64];    // [sum1(32)|sq1(32)]
__device__ __align__(16) __nv_bfloat16 g_w2hi[64*512],  g_w2lo[64*512];
__device__ __align__(16) __nv_bfloat16 g_w3hi[64*576],  g_w3lo[64*576];
__device__ __align__(16) __nv_bfloat16 g_wfhi[512*3136], g_wflo[512*3136];

// ================= helpers =================
__device__ __forceinline__ uint32_t smem_u32(const void* p) {
    return (uint32_t)__cvta_generic_to_shared(p);
}
#define CP16(dst_u32, src_ptr) \
    asm volatile("cp.async.cg.shared.global [%0], [%1], 16;" :: "r"(dst_u32), "l"(src_ptr))
#define CP_COMMIT() asm volatile("cp.async.commit_group;" ::: "memory")
#define CP_WAIT(n)  asm volatile("cp.async.wait_group %0;" :: "n"(n) : "memory")
#define LDSM4(r0, r1, r2, r3, addr) \
    asm volatile("ldmatrix.sync.aligned.m8n8.x4.shared.b16 {%0,%1,%2,%3}, [%4];" \
        : "=r"(r0), "=r"(r1), "=r"(r2), "=r"(r3) : "r"(addr))

// ================= conv1 + fused BN1 stats: [128,4,84,84] -> h1[b][pix(400)][c(32)] =====
#define SMEM1 ((28224 + 256*33)*4)
__global__ void __launch_bounds__(256) k_conv1(const float* __restrict__ x,
                                               const float* __restrict__ w,
                                               const float* __restrict__ bias)
{
    extern __shared__ float sm[];
    float* s_in = sm;
    float* s_w  = sm + 28224;
    __shared__ float s_sum[32], s_sq[32];
    const int n = blockIdx.x, tid = threadIdx.x;
    const int lane = tid & 31;

    const float4* gx = (const float4*)(x + n*28224);
    for (int i = tid; i < 7056; i += 256) ((float4*)s_in)[i] = gx[i];
    for (int i = tid; i < 8192; i += 256) {
        int oc = i >> 8, tap = i & 255;
        s_w[tap*33 + oc] = w[i];
    }
    if (tid < 32) { s_sum[tid] = 0.f; s_sq[tid] = 0.f; }
    __syncthreads();

    float ch_sum[8], ch_sq[8];
    #pragma unroll
    for (int i = 0; i < 8; i++) { ch_sum[i] = 0.f; ch_sq[i] = 0.f; }

    for (int task = tid; task < 400; task += 256) {
        int ocg = task & 3, posg = task >> 2;
        int oc0 = ocg * 8, p0 = posg * 4;
        float acc[8][4];
        #pragma unroll
        for (int i = 0; i < 8; i++)
            #pragma unroll
            for (int j = 0; j < 4; j++) acc[i][j] = 0.f;
        int base[4];
        #pragma unroll
        for (int j = 0; j < 4; j++) {
            int p = p0 + j, oy = p / 20, ox = p - oy*20;
            base[j] = oy*4*84 + ox*4;
        }
        for (int ic = 0; ic < 4; ic++) {
            #pragma unroll
            for (int ky = 0; ky < 8; ky++) {
                int ib = ic*7056 + ky*84;
                const float* wrow = s_w + (ic*64 + ky*8)*33 + oc0;
                #pragma unroll
                for (int kx = 0; kx < 8; kx++) {
                    float in0 = s_in[base[0]+ib+kx];
                    float in1 = s_in[base[1]+ib+kx];
                    float in2 = s_in[base[2]+ib+kx];
                    float in3 = s_in[base[3]+ib+kx];
                    const float* wp = wrow + kx*33;
                    #pragma unroll
                    for (int i = 0; i < 8; i++) {
                        float wf = wp[i];
                        acc[i][0] += wf*in0; acc[i][1] += wf*in1;
                        acc[i][2] += wf*in2; acc[i][3] += wf*in3;
                    }
                }
            }
        }
        #pragma unroll
        for (int j = 0; j < 4; j++) {
            #pragma unroll
            for (int i = 0; i < 8; i++) {
                float val = acc[i][j] + bias[oc0+i];
                g_h1[(n*400 + p0+j)*32 + oc0+i] = val;
                ch_sum[i] += val; ch_sq[i] += val*val;
            }
        }
    }

    #pragma unroll
    for (int s = 16; s >= 4; s >>= 1) {
        #pragma unroll
        for (int i = 0; i < 8; i++) {
            ch_sum[i] += __shfl_down_sync(0xffffffffu, ch_sum[i], s);
            ch_sq[i]  += __shfl_down_sync(0xffffffffu, ch_sq[i],  s);
        }
    }
    if (lane < 4) {
        #pragma unroll
        for (int i = 0; i < 8; i++) {
            atomicAdd(&s_sum[lane*8 + i], ch_sum[i]);
            atomicAdd(&s_sq[lane*8 + i],  ch_sq[i]);
        }
    }
    __syncthreads();
    if (tid < 32)       atomicAdd(&g_bn1acc[tid], s_sum[tid]);
    else if (tid < 64)  atomicAdd(&g_bn1acc[tid], s_sq[tid - 32]);
}

// ================= LIF layer 1 (BN finalize inlined) -> bf16 spikes =================
__global__ void k_lif1(const float* __restrict__ gamma, const float* __restrict__ beta)
{
    int idx = blockIdx.x*blockDim.x + threadIdx.x;
    if (idx >= 128*400*32) return;
    int c = idx & 31;
    float m = g_bn1acc[c] * (1.f/51200.f);
    float var = g_bn1acc[32 + c] * (1.f/51200.f) - m*m;
    float a = (g_h1[idx] - m) * rsqrtf(var + 1e-5f) * gamma[c] + beta[c];
    float v = 0.f;
    #pragma unroll
    for (int t = 0; t < 8; t++) {
        v = v + (a - v)*0.5f;
        float s = (v >= 1.0f) ? 1.0f : 0.0f;
        g_s1b[t*1638400 + idx] = __float2bfloat16(s);
        v = v * (1.0f - s);
    }
}

// ================= combined weight split (all 3 layers) + BN accumulator zeroing ==========
template<int SEL>
__device__ __forceinline__ void wsplit_body(const float* __restrict__ src, int oc)
{
    constexpr int K   = (SEL == 0) ? 512 : (SEL == 1) ? 576 : 3136;
    constexpr int IC  = (SEL == 0) ? 32 : (SEL == 1) ? 64 : 64;
    constexpr int KHW = (SEL == 0) ? 16 : (SEL == 1) ? 9  : 49;
    __nv_bfloat16* hi = (SEL == 0) ? g_w2hi : (SEL == 1) ? g_w3hi : g_wfhi;
    __nv_bfloat16* lo = (SEL == 0) ? g_w2lo : (SEL == 1) ? g_w3lo : g_wflo;
    __shared__ float sfl[K];
    int tid = threadIdx.x;
    const float* row = src + (size_t)oc*K;
    for (int i = tid; i < K; i += 256) sfl[i] = row[i];
    __syncthreads();
    __nv_bfloat16* dh = hi + (size_t)oc*K;
    __nv_bfloat16* dl = lo + (size_t)oc*K;
    for (int i = tid; i < K; i += 256) {
        int kk = i / IC, ic = i - kk*IC;
        float w = sfl[ic*KHW + kk];
        __nv_bfloat16 h = __float2bfloat16(w);
        dh[i] = h;
        dl[i] = __float2bfloat16(w - __bfloat162float(h));
    }
}

__global__ void __launch_bounds__(256) k_wsplit_all(const float* __restrict__ w2,
                                                    const float* __restrict__ w3,
                                                    const float* __restrict__ wf)
{
    int b = blockIdx.x;
    if (b == 0) {
        g_bnacc[threadIdx.x] = 0.f;
        if (threadIdx.x < 64) g_bn1acc[threadIdx.x] = 0.f;
    }
    if (b < 64)        wsplit_body<0>(w2, b);
    else if (b < 128)  wsplit_body<1>(w3, b - 64);
    else               wsplit_body<2>(wf, b - 128);
}

// ====== bf16 mma.sync GEMM, 3-stage cp.async, ldmatrix fragments, fused BN stats ======
#define MMA_OP(d, a0,a1,a2,a3, b0,b1) \
    asm volatile("mma.sync.aligned.m16n8k16.row.col.f32.bf16.bf16.f32 " \
        "{%0,%1,%2,%3}, {%4,%5,%6,%7}, {%8,%9}, {%0,%1,%2,%3};" \
        : "+f"((d)[0]), "+f"((d)[1]), "+f"((d)[2]), "+f"((d)[3]) \
        : "r"(a0), "r"(a1), "r"(a2), "r"(a3), "r"(b0), "r"(b1))

template<int LAYER>
__global__ void __launch_bounds__(256) k_gemm(const float* __restrict__ bias)
{
    constexpr int K    = (LAYER == 0) ? 512 : (LAYER == 1) ? 576 : 3136;
    constexpr int NTOT = (LAYER == 2) ? 512 : 64;
    constexpr int NCH  = (LAYER == 0) ? 16 : (LAYER == 1) ? 18 : 49;
    const __nv_bfloat16* Asrc = (LAYER == 0) ? g_s1b : (LAYER == 1) ? g_s2b : g_s3b;
    const __nv_bfloat16* Bhi = (LAYER == 0) ? g_w2hi: (LAYER == 1) ? g_w3hi: g_wfhi;
    const __nv_bfloat16* Blo = (LAYER == 0) ? g_w2lo: (LAYER == 1) ? g_w3lo: g_wflo;
    float* C                 = (LAYER == 0) ? g_h2  : (LAYER == 1) ? g_h3
                                            : g_h4 + (size_t)blockIdx.z*524288;
    const int cbase = (LAYER == 2) ? blockIdx.z*49 : 0;

    __shared__ __align__(16) __nv_bfloat16 sA[3][128*40];
    __shared__ __align__(16) __nv_bfloat16 sBh[3][64*40];
    __shared__ __align__(16) __nv_bfloat16 sBl[3][64*40];
    __shared__ float bs[64], bq[64];

    const int tid = threadIdx.x;
    const int wid = tid >> 5, lane = tid & 31;
    const int gq = lane >> 2, q = lane & 3;
    const int wm = wid & 3, wn = wid >> 2;
    const int m0 = blockIdx.x * 128, n0 = blockIdx.y * 64;

    uint32_t uA[3]  = { smem_u32(sA[0]),  smem_u32(sA[1]),  smem_u32(sA[2]) };
    uint32_t uBh[3] = { smem_u32(sBh[0]), smem_u32(sBh[1]), smem_u32(sBh[2]) };
    uint32_t uBl[3] = { smem_u32(sBl[0]), smem_u32(sBl[1]), smem_u32(sBl[2]) };

    if (LAYER != 2 && tid < 64) { bs[tid] = 0.f; bq[tid] = 0.f; }

    // ldmatrix lane offsets (bytes): matrix slot mlo = lane>>3, row-in-matrix lr = lane&7
    const int mlo = lane >> 3, lr = lane & 7;
    uint32_t aoffL[2][2], boffL[2][2];
    #pragma unroll
    for (int mi = 0; mi < 2; mi++)
        #pragma unroll
        for (int ks = 0; ks < 2; ks++) {
            int rowA = wm*32 + mi*16 + (mlo & 1)*8 + lr;
            aoffL[mi][ks] = (uint32_t)(rowA*80 + ks*32 + (mlo >> 1)*16);
        }
    #pragma unroll
    for (int pi = 0; pi < 2; pi++)
        #pragma unroll
        for (int ks = 0; ks < 2; ks++) {
            int nt = pi*2 + (mlo >> 1);
            int rowB = wn*32 + nt*8 + lr;
            boffL[pi][ks] = (uint32_t)(rowB*80 + ks*32 + (mlo & 1)*16);
        }

    const int gg = tid & 3;
    size_t abase[2];
    uint32_t adst[2];
    #pragma unroll
    for (int it = 0; it < 2; it++) {
        int r = (tid >> 2) + it*64;
        int rg = m0 + r;
        if (LAYER == 0) {
            int tb = rg / 81, pos = rg - tb*81;
            int oy = pos / 9, ox = pos - oy*9;
            abase[it] = (size_t)tb*12800 + (size_t)(oy*40 + ox*2)*32 + gg*8;
        } else if (LAYER == 1) {
            int tb = rg / 49, pos = rg - tb*49;
            int oy = pos / 7, ox = pos - oy*7;
            abase[it] = (size_t)tb*5184 + (size_t)(oy*9 + ox)*64 + gg*8;
        } else {
            abase[it] = (size_t)rg*3136 + gg*8;
        }
        adst[it] = (uint32_t)(r*40 + gg*8)*2;
    }

    auto load_chunk = [&](int cc, int buf) {
        int aoff;
        if (LAYER == 0) {
            int ky = cc >> 2, kx = cc & 3;
            aoff = (ky*20 + kx)*32;
        } else if (LAYER == 1) {
            int kk = cc >> 1, half = cc & 1;
            int ky = kk / 3, kx = kk - ky*3;
            aoff = (ky*9 + kx)*64 + half*32;
        } else {
            aoff = (cbase + cc) << 5;
        }
        #pragma unroll
        for (int it = 0; it < 2; it++)
            CP16(uA[buf] + adst[it], Asrc + abase[it] + aoff);
        int k0 = (cbase + cc) << 5;
        int r = tid >> 2;
        CP16(uBh[buf] + (uint32_t)(r*40 + gg*8)*2, Bhi + (size_t)(n0 + r)*K + k0 + gg*8);
        CP16(uBl[buf] + (uint32_t)(r*40 + gg*8)*2, Blo + (size_t)(n0 + r)*K + k0 + gg*8);
    };

    float acc[2][4][4];
    #pragma unroll
    for (int mi = 0; mi < 2; mi++)
        #pragma unroll
        for (int nt = 0; nt < 4; nt++)
            #pragma unroll
            for (int j = 0; j < 4; j++) acc[mi][nt][j] = 0.f;

    load_chunk(0, 0); CP_COMMIT();
    load_chunk(1, 1); CP_COMMIT();

    for (int c = 0; c < NCH; c++) {
        int buf = c % 3;
        if (c + 1 < NCH) CP_WAIT(1); else CP_WAIT(0);
        __syncthreads();

        uint32_t uAb = uA[buf], uBhb = uBh[buf], uBlb = uBl[buf];
        #pragma unroll
        for (int ks = 0; ks < 2; ks++) {
            uint32_t a[2][4], bh[2][4], bl[2][4];
            LDSM4(a[0][0], a[0][1], a[0][2], a[0][3], uAb + aoffL[0][ks]);
            LDSM4(a[1][0], a[1][1], a[1][2], a[1][3], uAb + aoffL[1][ks]);
            LDSM4(bh[0][0], bh[0][1], bh[0][2], bh[0][3], uBhb + boffL[0][ks]);
            LDSM4(bh[1][0], bh[1][1], bh[1][2], bh[1][3], uBhb + boffL[1][ks]);
            LDSM4(bl[0][0], bl[0][1], bl[0][2], bl[0][3], uBlb + boffL[0][ks]);
            LDSM4(bl[1][0], bl[1][1], bl[1][2], bl[1][3], uBlb + boffL[1][ks]);
            #pragma unroll
            for (int pi = 0; pi < 2; pi++)
                #pragma unroll
                for (int j = 0; j < 2; j++) {
                    int nt = pi*2 + j;
                    uint32_t b0 = bh[pi][j*2], b1 = bh[pi][j*2+1];
                    MMA_OP(acc[0][nt], a[0][0],a[0][1],a[0][2],a[0][3], b0, b1);
                    MMA_OP(acc[1][nt], a[1][0],a[1][1],a[1][2],a[1][3], b0, b1);
                    b0 = bl[pi][j*2]; b1 = bl[pi][j*2+1];
                    MMA_OP(acc[0][nt], a[0][0],a[0][1],a[0][2],a[0][3], b0, b1);
                    MMA_OP(acc[1][nt], a[1][0],a[1][1],a[1][2],a[1][3], b0, b1);
                }
        }
        __syncthreads();
        if (c + 2 < NCH) { load_chunk(c + 2, (c + 2) % 3); CP_COMMIT(); }
    }

    // epilogue: store + fused BN column sums (LAYER 0/1)
    float csum[4][2], csq[4][2];
    #pragma unroll
    for (int nt = 0; nt < 4; nt++) { csum[nt][0]=0.f; csum[nt][1]=0.f; csq[nt][0]=0.f; csq[nt][1]=0.f; }

    #pragma unroll
    for (int mi = 0; mi < 2; mi++) {
        int r0 = m0 + wm*32 + mi*16 + gq;
        #pragma unroll
        for (int nt = 0; nt < 4; nt++) {
            int n = n0 + wn*32 + nt*8 + q*2;
            float b0 = 0.f, b1 = 0.f;
            if (LAYER != 2) { b0 = bias[n]; b1 = bias[n+1]; }
            float v00 = acc[mi][nt][0] + b0, v01 = acc[mi][nt][1] + b1;
            float v10 = acc[mi][nt][2] + b0, v11 = acc[mi][nt][3] + b1;
            float2 w0; w0.x = v00; w0.y = v01;
            float2 w1; w1.x = v10; w1.y = v11;
            *(float2*)(C + (size_t)r0*NTOT + n) = w0;
            *(float2*)(C + (size_t)(r0+8)*NTOT + n) = w1;
            if (LAYER != 2) {
                csum[nt][0] += v00 + v10;  csq[nt][0] += v00*v00 + v10*v10;
                csum[nt][1] += v01 + v11;  csq[nt][1] += v01*v01 + v11*v11;
            }
        }
    }

    if (LAYER != 2) {
        #pragma unroll
        for (int s = 16; s >= 4; s >>= 1) {
            #pragma unroll
            for (int nt = 0; nt < 4; nt++) {
                csum[nt][0] += __shfl_down_sync(0xffffffffu, csum[nt][0], s);
                csum[nt][1] += __shfl_down_sync(0xffffffffu, csum[nt][1], s);
                csq[nt][0]  += __shfl_down_sync(0xffffffffu, csq[nt][0],  s);
                csq[nt][1]  += __shfl_down_sync(0xffffffffu, csq[nt][1],  s);
            }
        }
        __syncthreads();
        if (gq == 0) {
            #pragma unroll
            for (int nt = 0; nt < 4; nt++) {
                int co = wn*32 + nt*8 + q*2;
                atomicAdd(&bs[co],   csum[nt][0]);
                atomicAdd(&bs[co+1], csum[nt][1]);
                atomicAdd(&bq[co],   csq[nt][0]);
                atomicAdd(&bq[co+1], csq[nt][1]);
            }
        }
        __syncthreads();
        float* gsum = (LAYER == 0) ? g_bnacc      : g_bnacc + 128;
        float* gsq  = (LAYER == 0) ? g_bnacc + 64 : g_bnacc + 192;
        if (tid < 64)        atomicAdd(&gsum[tid], bs[tid]);
        else if (tid < 128)  atomicAdd(&gsq[tid-64], bq[tid-64]);
    }
}

// ================= LIF layer 2 (BN finalize inlined), planar, coalesced =================
__global__ void k_lif2(const float* __restrict__ gamma, const float* __restrict__ beta)
{
    int idx = blockIdx.x*blockDim.x + threadIdx.x;
    if (idx >= 128*81*64) return;
    int c = idx & 63;
    float m = g_bnacc[c] * (1.f/82944.f);
    float var = g_bnacc[64 + c] * (1.f/82944.f) - m*m;
    float sc = rsqrtf(var + 1e-5f) * gamma[c];
    float be = beta[c];
    float v = 0.f;
    #pragma unroll
    for (int t = 0; t < 8; t++) {
        float a = (g_h2[(size_t)t*663552 + idx] - m)*sc + be;
        v = v + (a - v)*0.5f;
        float s = (v >= 1.0f) ? 1.0f : 0.0f;
        g_s2b[(size_t)t*663552 + idx] = __float2bfloat16(s);
        v = v * (1.0f - s);
    }
}

// ================= LIF layer 3 (BN finalize inlined), planar =================
__global__ void k_lif3(const float* __restrict__ gamma, const float* __restrict__ beta)
{
    int idx = blockIdx.x*blockDim.x + threadIdx.x;
    if (idx >= 128*49*64) return;
    int c = idx & 63;
    float m = g_bnacc[128 + c] * (1.f/50176.f);
    float var = g_bnacc[192 + c] * (1.f/50176.f) - m*m;
    float sc = rsqrtf(var + 1e-5f) * gamma[c];
    float be = beta[c];
    float v = 0.f;
    #pragma unroll
    for (int t = 0; t < 8; t++) {
        float a = (g_h3[(size_t)t*401408 + idx] - m)*sc + be;
        v = v + (a - v)*0.5f;
        float s = (v >= 1.0f) ? 1.0f : 0.0f;
        g_s3b[(size_t)t*401408 + idx] = __float2bfloat16(s);
        v = v * (1.0f - s);
    }
}

// ================= tail: LIF4 + fco + mean over T, one block per batch =================
__global__ void __launch_bounds__(512) k_tail(const float* __restrict__ fb,
                                              const float* __restrict__ fco_w,
                                              const float* __restrict__ fco_b,
                                              float* __restrict__ out)
{
    __shared__ float s0[512], s1[512];
    int b = blockIdx.x, o = threadIdx.x;
    float bb = fb[o];
    float v = 0.f, cnt = 0.f;
    #pragma unroll
    for (int t = 0; t < 8; t++) {
        int j = (t*128 + b)*512 + o;
        float a = g_h4[j] + g_h4[524288 + j] + bb;
        v = v + (a - v)*0.5f;
        float s = (v >= 1.0f) ? 1.0f : 0.0f;
        cnt += s;
        v = v * (1.0f - s);
    }
    s0[o] = cnt * fco_w[o];
    s1[o] = cnt * fco_w[512 + o];
    __syncthreads();
    for (int k = 256; k > 0; k >>= 1) {
        if (o < k) { s0[o] += s0[o+k]; s1[o] += s1[o+k]; }
        __syncthreads();
    }
    if (o == 0) {
        out[b*2 + 0] = fco_b[0] + s0[0] * 0.125f;
        out[b*2 + 1] = fco_b[1] + s1[0] * 0.125f;
    }
}

// ================= launch =================
extern "C" void kernel_launch(void* const* d_in, const int* in_sizes, int n_in,
                              void* d_out, int out_size)
{
    const float* x   = (const float*)d_in[0];
    const float* c1w = (const float*)d_in[1];
    const float* c1b = (const float*)d_in[2];
    const float* g1  = (const float*)d_in[3];
    const float* b1  = (const float*)d_in[4];
    const float* c2w = (const float*)d_in[5];
    const float* c2b = (const float*)d_in[6];
    const float* g2  = (const float*)d_in[7];
    const float* b2  = (const float*)d_in[8];
    const float* c3w = (const float*)d_in[9];
    const float* c3b = (const float*)d_in[10];
    const float* g3  = (const float*)d_in[11];
    const float* b3  = (const float*)d_in[12];
    const float* fw  = (const float*)d_in[13];
    const float* fb  = (const float*)d_in[14];
    const float* ow  = (const float*)d_in[15];
    const float* ob  = (const float*)d_in[16];
    float* out = (float*)d_out;

    cudaFuncSetAttribute(k_conv1, cudaFuncAttributeMaxDynamicSharedMemorySize, SMEM1);

    k_wsplit_all<<<640, 256>>>(c2w, c3w, fw);

    k_conv1<<<128, 256, SMEM1>>>(x, c1w, c1b);
    k_lif1<<<(1638400 + 255)/256, 256>>>(g1, b1);

    k_gemm<0><<<dim3(648, 1), 256>>>(c2b);
    k_lif2<<<(663552 + 255)/256, 256>>>(g2, b2);

    k_gemm<1><<<dim3(392, 1), 256>>>(c3b);
    k_lif3<<<(401408 + 255)/256, 256>>>(g3, b3);

    k_gemm<2><<<dim3(8, 8, 2), 256>>>(fb);
    k_tail<<<128, 512>>>(fb, ow, ob, out);
}